// round 1
// baseline (speedup 1.0000x reference)
#include <cuda_runtime.h>
#include <cstdint>
#include <cstddef>

#define EDIM 1024
#define NHEAD 16
#define HDIM 64
#define FFDIM 4096
#define BATCH 4
#define SEQ 2048
#define NTOK (BATCH*SEQ)   // 8192

// ------------------- scratch (device globals; no allocations) -------------------
__device__ float g_qln[(size_t)NTOK*EDIM];
__device__ float g_vln[(size_t)NTOK*EDIM];
__device__ float g_kln[(size_t)NTOK*EDIM];
__device__ float g_Q  [(size_t)NTOK*EDIM];
__device__ float g_K  [(size_t)NTOK*EDIM];
__device__ float g_V  [(size_t)NTOK*EDIM];
__device__ float g_scores[(size_t)BATCH*NHEAD*SEQ*SEQ];   // 1 GB
__device__ float g_att[(size_t)NTOK*EDIM];
__device__ float g_x  [(size_t)NTOK*EDIM];
__device__ float g_h  [(size_t)NTOK*EDIM];
__device__ float g_ff [(size_t)NTOK*FFDIM];

// ------------------- helpers -------------------
__device__ __forceinline__ uint32_t f2tf(float f) {
    uint32_t u;
    asm("cvt.rna.tf32.f32 %0, %1;" : "=r"(u) : "f"(f));
    return u;
}

__device__ __forceinline__ void mma8(float* c, const uint32_t* a, const uint32_t* b) {
    asm volatile(
        "mma.sync.aligned.m16n8k8.row.col.f32.tf32.tf32.f32 "
        "{%0,%1,%2,%3},{%4,%5,%6,%7},{%8,%9},{%0,%1,%2,%3};\n"
        : "+f"(c[0]), "+f"(c[1]), "+f"(c[2]), "+f"(c[3])
        : "r"(a[0]), "r"(a[1]), "r"(a[2]), "r"(a[3]), "r"(b[0]), "r"(b[1]));
}

__device__ __forceinline__ float gelu_exact(float v) {
    return 0.5f * v * (1.0f + erff(v * 0.70710678118654752f));
}

// ------------------- LayerNorm -------------------
__global__ __launch_bounds__(256) void ln_kernel(
    const float* __restrict__ in, float* __restrict__ out,
    const float* __restrict__ gw, const float* __restrict__ gb)
{
    int row = blockIdx.x;
    int tid = threadIdx.x;
    const float4* inr = reinterpret_cast<const float4*>(in + (size_t)row * EDIM);
    float4 v = inr[tid];
    float s  = v.x + v.y + v.z + v.w;
    float sq = v.x*v.x + v.y*v.y + v.z*v.z + v.w*v.w;

    int lane = tid & 31, warp = tid >> 5;
    #pragma unroll
    for (int o = 16; o > 0; o >>= 1) {
        s  += __shfl_xor_sync(0xffffffffu, s, o);
        sq += __shfl_xor_sync(0xffffffffu, sq, o);
    }
    __shared__ float rs[8], rq[8];
    if (lane == 0) { rs[warp] = s; rq[warp] = sq; }
    __syncthreads();
    if (warp == 0) {
        float s2 = (lane < 8) ? rs[lane] : 0.0f;
        float q2 = (lane < 8) ? rq[lane] : 0.0f;
        #pragma unroll
        for (int o = 4; o > 0; o >>= 1) {
            s2 += __shfl_xor_sync(0xffffffffu, s2, o);
            q2 += __shfl_xor_sync(0xffffffffu, q2, o);
        }
        if (lane == 0) { rs[0] = s2; rq[0] = q2; }
    }
    __syncthreads();
    float mean = rs[0] * (1.0f / EDIM);
    float var  = rq[0] * (1.0f / EDIM) - mean * mean;
    float rstd = rsqrtf(var + 1e-5f);

    float4 gg = reinterpret_cast<const float4*>(gw)[tid];
    float4 bb = reinterpret_cast<const float4*>(gb)[tid];
    float4 o4;
    o4.x = (v.x - mean) * rstd * gg.x + bb.x;
    o4.y = (v.y - mean) * rstd * gg.y + bb.y;
    o4.z = (v.z - mean) * rstd * gg.z + bb.z;
    o4.w = (v.w - mean) * rstd * gg.w + bb.w;
    reinterpret_cast<float4*>(out + (size_t)row * EDIM)[tid] = o4;
}

// ------------------- masked softmax over rows of length SEQ -------------------
__global__ __launch_bounds__(256) void softmax_kernel(
    float* __restrict__ sc, const int* __restrict__ mask)
{
    size_t row = blockIdx.x;                 // 0 .. B*H*S-1
    int b = (int)(row / ((size_t)NHEAD * SEQ));
    float* p = sc + row * SEQ;
    const int* mrow = mask + (size_t)b * SEQ;

    int tid = threadIdx.x;
    int base = tid * 8;
    float v[8];
    float4 x0 = *reinterpret_cast<const float4*>(p + base);
    float4 x1 = *reinterpret_cast<const float4*>(p + base + 4);
    v[0]=x0.x; v[1]=x0.y; v[2]=x0.z; v[3]=x0.w;
    v[4]=x1.x; v[5]=x1.y; v[6]=x1.z; v[7]=x1.w;
    int4 m0 = *reinterpret_cast<const int4*>(mrow + base);
    int4 m1 = *reinterpret_cast<const int4*>(mrow + base + 4);
    if (m0.x == 0) v[0] = -1e20f;
    if (m0.y == 0) v[1] = -1e20f;
    if (m0.z == 0) v[2] = -1e20f;
    if (m0.w == 0) v[3] = -1e20f;
    if (m1.x == 0) v[4] = -1e20f;
    if (m1.y == 0) v[5] = -1e20f;
    if (m1.z == 0) v[6] = -1e20f;
    if (m1.w == 0) v[7] = -1e20f;

    float mx = v[0];
    #pragma unroll
    for (int i = 1; i < 8; i++) mx = fmaxf(mx, v[i]);
    int lane = tid & 31, warp = tid >> 5;
    #pragma unroll
    for (int o = 16; o > 0; o >>= 1) mx = fmaxf(mx, __shfl_xor_sync(0xffffffffu, mx, o));
    __shared__ float red[8];
    if (lane == 0) red[warp] = mx;
    __syncthreads();
    if (warp == 0) {
        float m2 = (lane < 8) ? red[lane] : -1e30f;
        #pragma unroll
        for (int o = 4; o > 0; o >>= 1) m2 = fmaxf(m2, __shfl_xor_sync(0xffffffffu, m2, o));
        if (lane == 0) red[0] = m2;
    }
    __syncthreads();
    mx = red[0];
    __syncthreads();

    float sum = 0.0f;
    #pragma unroll
    for (int i = 0; i < 8; i++) { v[i] = expf(v[i] - mx); sum += v[i]; }
    #pragma unroll
    for (int o = 16; o > 0; o >>= 1) sum += __shfl_xor_sync(0xffffffffu, sum, o);
    if (lane == 0) red[warp] = sum;
    __syncthreads();
    if (warp == 0) {
        float s2 = (lane < 8) ? red[lane] : 0.0f;
        #pragma unroll
        for (int o = 4; o > 0; o >>= 1) s2 += __shfl_xor_sync(0xffffffffu, s2, o);
        if (lane == 0) red[0] = s2;
    }
    __syncthreads();
    float inv = 1.0f / red[0];

    float4 y0, y1;
    y0.x=v[0]*inv; y0.y=v[1]*inv; y0.z=v[2]*inv; y0.w=v[3]*inv;
    y1.x=v[4]*inv; y1.y=v[5]*inv; y1.z=v[6]*inv; y1.w=v[7]*inv;
    *reinterpret_cast<float4*>(p + base)     = y0;
    *reinterpret_cast<float4*>(p + base + 4) = y1;
}

// ------------------- tf32 GEMM -------------------
// C[M,N] = alpha * A[M,K] @ op(B) (+ epilogue)
//   BT=false: B is [K,N] row-major (NN)
//   BT=true : B is [N,K] row-major (TN, i.e. C = A @ B^T)
// EPI: 0 = none, 1 = +bias, 2 = +bias +res, 3 = gelu(acc + bias)
// batching: if innerB>0, per-z offsets: (z/innerB)*Outer + (z%innerB)*Inner
template<int BN, bool BT, int EPI>
__global__ __launch_bounds__(256) void gemm_tf32(
    const float* __restrict__ A, const float* __restrict__ Bm, float* __restrict__ C,
    int lda, int ldb, int ldc, int K, float alpha,
    const float* __restrict__ bias, const float* __restrict__ res,
    long long aO, long long aI, long long bO, long long bI,
    long long cO, long long cI, int innerB)
{
    constexpr int BM = 128, BK = 32;
    constexpr int WN = BN / 4;          // 4 warp-columns
    constexpr int NFRAG = WN / 8;

    int z = blockIdx.z;
    if (innerB > 0) {
        long long zo = z / innerB, zi = z % innerB;
        A  += zo * aO + zi * aI;
        Bm += zo * bO + zi * bI;
        C  += zo * cO + zi * cI;
    }
    int m0 = blockIdx.y * BM;
    int n0 = blockIdx.x * BN;
    int tid = threadIdx.x;
    int warp = tid >> 5, lane = tid & 31;
    int wm = (warp >> 2) * 64;          // 2 warp-rows of 64
    int wn = (warp & 3) * WN;
    int g  = lane >> 2, t4 = lane & 3;

    __shared__ uint32_t As[BM * 33];
    __shared__ uint32_t Bs[BT ? (BN * 33) : (BK * (BN + 1))];

    float acc[4][NFRAG][4];
    #pragma unroll
    for (int i = 0; i < 4; i++)
        #pragma unroll
        for (int j = 0; j < NFRAG; j++)
            #pragma unroll
            for (int q = 0; q < 4; q++) acc[i][j][q] = 0.0f;

    for (int k0 = 0; k0 < K; k0 += BK) {
        // ---- load A tile [BM x BK] ----
        #pragma unroll
        for (int it = 0; it < (BM * 8) / 256; it++) {
            int idx = tid + it * 256;
            int r = idx >> 3, c4 = (idx & 7) * 4;
            float4 val = *reinterpret_cast<const float4*>(A + (size_t)(m0 + r) * lda + k0 + c4);
            As[r * 33 + c4 + 0] = f2tf(val.x);
            As[r * 33 + c4 + 1] = f2tf(val.y);
            As[r * 33 + c4 + 2] = f2tf(val.z);
            As[r * 33 + c4 + 3] = f2tf(val.w);
        }
        // ---- load B tile ----
        if (BT) {
            #pragma unroll
            for (int it = 0; it < (BN * 8) / 256; it++) {
                int idx = tid + it * 256;
                int r = idx >> 3, c4 = (idx & 7) * 4;
                float4 val = *reinterpret_cast<const float4*>(Bm + (size_t)(n0 + r) * ldb + k0 + c4);
                Bs[r * 33 + c4 + 0] = f2tf(val.x);
                Bs[r * 33 + c4 + 1] = f2tf(val.y);
                Bs[r * 33 + c4 + 2] = f2tf(val.z);
                Bs[r * 33 + c4 + 3] = f2tf(val.w);
            }
        } else {
            constexpr int NV = BN / 4;
            #pragma unroll
            for (int it = 0; it < (BK * NV) / 256; it++) {
                int idx = tid + it * 256;
                int r = idx / NV, c4 = (idx % NV) * 4;
                float4 val = *reinterpret_cast<const float4*>(Bm + (size_t)(k0 + r) * ldb + n0 + c4);
                Bs[r * (BN + 1) + c4 + 0] = f2tf(val.x);
                Bs[r * (BN + 1) + c4 + 1] = f2tf(val.y);
                Bs[r * (BN + 1) + c4 + 2] = f2tf(val.z);
                Bs[r * (BN + 1) + c4 + 3] = f2tf(val.w);
            }
        }
        __syncthreads();

        #pragma unroll
        for (int kk = 0; kk < BK; kk += 8) {
            uint32_t afr[4][4];
            uint32_t bfr[NFRAG][2];
            #pragma unroll
            for (int mf = 0; mf < 4; mf++) {
                int mr = wm + mf * 16 + g;
                afr[mf][0] = As[mr * 33 + kk + t4];
                afr[mf][1] = As[(mr + 8) * 33 + kk + t4];
                afr[mf][2] = As[mr * 33 + kk + t4 + 4];
                afr[mf][3] = As[(mr + 8) * 33 + kk + t4 + 4];
            }
            #pragma unroll
            for (int nf = 0; nf < NFRAG; nf++) {
                int n = wn + nf * 8 + g;
                if (BT) {
                    bfr[nf][0] = Bs[n * 33 + kk + t4];
                    bfr[nf][1] = Bs[n * 33 + kk + t4 + 4];
                } else {
                    bfr[nf][0] = Bs[(kk + t4) * (BN + 1) + n];
                    bfr[nf][1] = Bs[(kk + t4 + 4) * (BN + 1) + n];
                }
            }
            #pragma unroll
            for (int mf = 0; mf < 4; mf++)
                #pragma unroll
                for (int nf = 0; nf < NFRAG; nf++)
                    mma8(acc[mf][nf], afr[mf], bfr[nf]);
        }
        __syncthreads();
    }

    // ---- epilogue ----
    #pragma unroll
    for (int mf = 0; mf < 4; mf++) {
        #pragma unroll
        for (int nf = 0; nf < NFRAG; nf++) {
            #pragma unroll
            for (int i = 0; i < 4; i++) {
                int m = m0 + wm + mf * 16 + g + ((i >= 2) ? 8 : 0);
                int n = n0 + wn + nf * 8 + t4 * 2 + (i & 1);
                float v = acc[mf][nf][i] * alpha;
                if (EPI >= 1) v += bias[n];
                if (EPI == 2) v += res[(size_t)m * ldc + n];
                if (EPI == 3) v = gelu_exact(v);
                C[(size_t)m * ldc + n] = v;
            }
        }
    }
}

// ------------------- host launch -------------------
static float* sym_addr(const void* symbol) {
    void* p = nullptr;
    cudaGetSymbolAddress(&p, symbol);
    return reinterpret_cast<float*>(p);
}

extern "C" void kernel_launch(void* const* d_in, const int* in_sizes, int n_in,
                              void* d_out, int out_size) {
    (void)in_sizes; (void)n_in; (void)out_size;
    const float* value = (const float*)d_in[0];
    const float* key   = (const float*)d_in[1];
    const float* query = (const float*)d_in[2];
    const int*   mask  = (const int*)  d_in[3];
    const float* Wv    = (const float*)d_in[4];
    const float* Wk    = (const float*)d_in[5];
    const float* Wq    = (const float*)d_in[6];
    const float* Wo    = (const float*)d_in[7];
    const float* bo    = (const float*)d_in[8];
    const float* ln1_g = (const float*)d_in[9];
    const float* ln1_b = (const float*)d_in[10];
    const float* ln2_g = (const float*)d_in[11];
    const float* ln2_b = (const float*)d_in[12];
    const float* lnf_g = (const float*)d_in[13];
    const float* lnf_b = (const float*)d_in[14];
    const float* W1    = (const float*)d_in[15];
    const float* b1    = (const float*)d_in[16];
    const float* W2    = (const float*)d_in[17];
    const float* b2    = (const float*)d_in[18];
    float* out = (float*)d_out;

    float* p_qln = sym_addr(g_qln);
    float* p_vln = sym_addr(g_vln);
    float* p_kln = sym_addr(g_kln);
    float* p_Q   = sym_addr(g_Q);
    float* p_K   = sym_addr(g_K);
    float* p_V   = sym_addr(g_V);
    float* p_sc  = sym_addr(g_scores);
    float* p_att = sym_addr(g_att);
    float* p_x   = sym_addr(g_x);
    float* p_h   = sym_addr(g_h);
    float* p_ff  = sym_addr(g_ff);

    // 1) pre-norms
    ln_kernel<<<NTOK, 256>>>(query, p_qln, ln1_g, ln1_b);
    ln_kernel<<<NTOK, 256>>>(value, p_vln, ln2_g, ln2_b);
    ln_kernel<<<NTOK, 256>>>(key,   p_kln, ln2_g, ln2_b);

    // 2) QKV projections
    dim3 gProj(EDIM / 128, NTOK / 128, 1);
    gemm_tf32<128, false, 0><<<gProj, 256>>>(p_qln, Wq, p_Q, EDIM, EDIM, EDIM, EDIM,
        1.0f, nullptr, nullptr, 0, 0, 0, 0, 0, 0, 0);
    gemm_tf32<128, false, 0><<<gProj, 256>>>(p_kln, Wk, p_K, EDIM, EDIM, EDIM, EDIM,
        1.0f, nullptr, nullptr, 0, 0, 0, 0, 0, 0, 0);
    gemm_tf32<128, false, 0><<<gProj, 256>>>(p_vln, Wv, p_V, EDIM, EDIM, EDIM, EDIM,
        1.0f, nullptr, nullptr, 0, 0, 0, 0, 0, 0, 0);

    // 3) energy = (Q @ K^T) / 8, batched per (b,h)
    dim3 gQK(SEQ / 128, SEQ / 128, BATCH * NHEAD);
    gemm_tf32<128, true, 0><<<gQK, 256>>>(p_Q, p_K, p_sc, EDIM, EDIM, SEQ, HDIM,
        0.125f, nullptr, nullptr,
        (long long)SEQ * EDIM, HDIM,
        (long long)SEQ * EDIM, HDIM,
        (long long)NHEAD * SEQ * SEQ, (long long)SEQ * SEQ, NHEAD);

    // 4) masked softmax
    softmax_kernel<<<BATCH * NHEAD * SEQ, 256>>>(p_sc, mask);

    // 5) out = attn @ V, batched per (b,h)
    dim3 gAV(1, SEQ / 128, BATCH * NHEAD);
    gemm_tf32<64, false, 0><<<gAV, 256>>>(p_sc, p_V, p_att, SEQ, EDIM, EDIM, SEQ,
        1.0f, nullptr, nullptr,
        (long long)NHEAD * SEQ * SEQ, (long long)SEQ * SEQ,
        (long long)SEQ * EDIM, HDIM,
        (long long)SEQ * EDIM, HDIM, NHEAD);

    // 6) x = att @ Wo + bo + q_ln
    gemm_tf32<128, false, 2><<<gProj, 256>>>(p_att, Wo, p_x, EDIM, EDIM, EDIM, EDIM,
        1.0f, bo, p_qln, 0, 0, 0, 0, 0, 0, 0);

    // 7) h = LN_f(x)
    ln_kernel<<<NTOK, 256>>>(p_x, p_h, lnf_g, lnf_b);

    // 8) ff = gelu(h @ W1 + b1)
    dim3 gF1(FFDIM / 128, NTOK / 128, 1);
    gemm_tf32<128, false, 3><<<gF1, 256>>>(p_h, W1, p_ff, EDIM, FFDIM, FFDIM, EDIM,
        1.0f, b1, nullptr, 0, 0, 0, 0, 0, 0, 0);

    // 9) out = ff @ W2 + b2 + x
    dim3 gF2(EDIM / 128, NTOK / 128, 1);
    gemm_tf32<128, false, 2><<<gF2, 256>>>(p_ff, W2, out, FFDIM, EDIM, EDIM, FFDIM,
        1.0f, b2, p_x, 0, 0, 0, 0, 0, 0, 0);
}

// round 2
// speedup vs baseline: 1.7558x; 1.7558x over previous
#include <cuda_runtime.h>
#include <cstdint>
#include <cstddef>

#define EDIM 1024
#define NHEAD 16
#define HDIM 64
#define FFDIM 4096
#define BATCH 4
#define SEQ 2048
#define NTOK (BATCH*SEQ)   // 8192

// ------------------- scratch (device globals; no allocations) -------------------
__device__ float g_qln[(size_t)NTOK*EDIM];
__device__ float g_vln[(size_t)NTOK*EDIM];
__device__ float g_kln[(size_t)NTOK*EDIM];
__device__ float g_Q  [(size_t)NTOK*EDIM];
__device__ float g_K  [(size_t)NTOK*EDIM];
__device__ float g_V  [(size_t)NTOK*EDIM];
__device__ float g_scores[(size_t)BATCH*NHEAD*SEQ*SEQ];   // 1 GB
__device__ float g_att[(size_t)NTOK*EDIM];
__device__ float g_x  [(size_t)NTOK*EDIM];
__device__ float g_h  [(size_t)NTOK*EDIM];
__device__ float g_ff [(size_t)NTOK*FFDIM];

// ------------------- helpers -------------------
__device__ __forceinline__ uint32_t f2tf(float f) {
    uint32_t u;
    asm("cvt.rna.tf32.f32 %0, %1;" : "=r"(u) : "f"(f));
    return u;
}

__device__ __forceinline__ void mma8(float* c, const uint32_t* a, const uint32_t* b) {
    asm volatile(
        "mma.sync.aligned.m16n8k8.row.col.f32.tf32.tf32.f32 "
        "{%0,%1,%2,%3},{%4,%5,%6,%7},{%8,%9},{%0,%1,%2,%3};\n"
        : "+f"(c[0]), "+f"(c[1]), "+f"(c[2]), "+f"(c[3])
        : "r"(a[0]), "r"(a[1]), "r"(a[2]), "r"(a[3]), "r"(b[0]), "r"(b[1]));
}

__device__ __forceinline__ float gelu_exact(float v) {
    return 0.5f * v * (1.0f + erff(v * 0.70710678118654752f));
}

// ------------------- LayerNorm -------------------
__global__ __launch_bounds__(256) void ln_kernel(
    const float* __restrict__ in, float* __restrict__ out,
    const float* __restrict__ gw, const float* __restrict__ gb)
{
    int row = blockIdx.x;
    int tid = threadIdx.x;
    const float4* inr = reinterpret_cast<const float4*>(in + (size_t)row * EDIM);
    float4 v = inr[tid];
    float s  = v.x + v.y + v.z + v.w;
    float sq = v.x*v.x + v.y*v.y + v.z*v.z + v.w*v.w;

    int lane = tid & 31, warp = tid >> 5;
    #pragma unroll
    for (int o = 16; o > 0; o >>= 1) {
        s  += __shfl_xor_sync(0xffffffffu, s, o);
        sq += __shfl_xor_sync(0xffffffffu, sq, o);
    }
    __shared__ float rs[8], rq[8];
    if (lane == 0) { rs[warp] = s; rq[warp] = sq; }
    __syncthreads();
    if (warp == 0) {
        float s2 = (lane < 8) ? rs[lane] : 0.0f;
        float q2 = (lane < 8) ? rq[lane] : 0.0f;
        #pragma unroll
        for (int o = 4; o > 0; o >>= 1) {
            s2 += __shfl_xor_sync(0xffffffffu, s2, o);
            q2 += __shfl_xor_sync(0xffffffffu, q2, o);
        }
        if (lane == 0) { rs[0] = s2; rq[0] = q2; }
    }
    __syncthreads();
    float mean = rs[0] * (1.0f / EDIM);
    float var  = rq[0] * (1.0f / EDIM) - mean * mean;
    float rstd = rsqrtf(var + 1e-5f);

    float4 gg = reinterpret_cast<const float4*>(gw)[tid];
    float4 bb = reinterpret_cast<const float4*>(gb)[tid];
    float4 o4;
    o4.x = (v.x - mean) * rstd * gg.x + bb.x;
    o4.y = (v.y - mean) * rstd * gg.y + bb.y;
    o4.z = (v.z - mean) * rstd * gg.z + bb.z;
    o4.w = (v.w - mean) * rstd * gg.w + bb.w;
    reinterpret_cast<float4*>(out + (size_t)row * EDIM)[tid] = o4;
}

// ------------------- masked softmax over rows of length SEQ -------------------
__global__ __launch_bounds__(256) void softmax_kernel(
    float* __restrict__ sc, const int* __restrict__ mask)
{
    size_t row = blockIdx.x;                 // 0 .. B*H*S-1
    int b = (int)(row / ((size_t)NHEAD * SEQ));
    float* p = sc + row * SEQ;
    const int* mrow = mask + (size_t)b * SEQ;

    int tid = threadIdx.x;
    int base = tid * 8;
    float v[8];
    float4 x0 = *reinterpret_cast<const float4*>(p + base);
    float4 x1 = *reinterpret_cast<const float4*>(p + base + 4);
    v[0]=x0.x; v[1]=x0.y; v[2]=x0.z; v[3]=x0.w;
    v[4]=x1.x; v[5]=x1.y; v[6]=x1.z; v[7]=x1.w;
    int4 m0 = *reinterpret_cast<const int4*>(mrow + base);
    int4 m1 = *reinterpret_cast<const int4*>(mrow + base + 4);
    if (m0.x == 0) v[0] = -1e20f;
    if (m0.y == 0) v[1] = -1e20f;
    if (m0.z == 0) v[2] = -1e20f;
    if (m0.w == 0) v[3] = -1e20f;
    if (m1.x == 0) v[4] = -1e20f;
    if (m1.y == 0) v[5] = -1e20f;
    if (m1.z == 0) v[6] = -1e20f;
    if (m1.w == 0) v[7] = -1e20f;

    float mx = v[0];
    #pragma unroll
    for (int i = 1; i < 8; i++) mx = fmaxf(mx, v[i]);
    int lane = tid & 31, warp = tid >> 5;
    #pragma unroll
    for (int o = 16; o > 0; o >>= 1) mx = fmaxf(mx, __shfl_xor_sync(0xffffffffu, mx, o));
    __shared__ float red[8];
    if (lane == 0) red[warp] = mx;
    __syncthreads();
    if (warp == 0) {
        float m2 = (lane < 8) ? red[lane] : -1e30f;
        #pragma unroll
        for (int o = 4; o > 0; o >>= 1) m2 = fmaxf(m2, __shfl_xor_sync(0xffffffffu, m2, o));
        if (lane == 0) red[0] = m2;
    }
    __syncthreads();
    mx = red[0];
    __syncthreads();

    float sum = 0.0f;
    #pragma unroll
    for (int i = 0; i < 8; i++) { v[i] = expf(v[i] - mx); sum += v[i]; }
    #pragma unroll
    for (int o = 16; o > 0; o >>= 1) sum += __shfl_xor_sync(0xffffffffu, sum, o);
    if (lane == 0) red[warp] = sum;
    __syncthreads();
    if (warp == 0) {
        float s2 = (lane < 8) ? red[lane] : 0.0f;
        #pragma unroll
        for (int o = 4; o > 0; o >>= 1) s2 += __shfl_xor_sync(0xffffffffu, s2, o);
        if (lane == 0) red[0] = s2;
    }
    __syncthreads();
    float inv = 1.0f / red[0];

    float4 y0, y1;
    y0.x=v[0]*inv; y0.y=v[1]*inv; y0.z=v[2]*inv; y0.w=v[3]*inv;
    y1.x=v[4]*inv; y1.y=v[5]*inv; y1.z=v[6]*inv; y1.w=v[7]*inv;
    *reinterpret_cast<float4*>(p + base)     = y0;
    *reinterpret_cast<float4*>(p + base + 4) = y1;
}

// ------------------- tf32 GEMM -------------------
// C[M,N] = alpha * A[M,K] @ op(B) (+ epilogue)
//   BT=false: B is [K,N] row-major (NN)
//   BT=true : B is [N,K] row-major (TN, i.e. C = A @ B^T)
// EPI: 0 = none, 1 = +bias, 2 = +bias +res, 3 = gelu(acc + bias)
// Conflict-free smem layouts:
//   k-major tiles (A, BT-B): row stride 36 -> fragment bank (4g + t4) % 32, bijective.
//   NN B tile:   row stride BN+8 -> fragment bank (8*t4 + g) % 32, bijective.
//   All tile stores are STS.128 (each 8-lane phase covers 32 consecutive words).
template<int BN, bool BT, int EPI>
__global__ __launch_bounds__(256) void gemm_tf32(
    const float* __restrict__ A, const float* __restrict__ Bm, float* __restrict__ C,
    int lda, int ldb, int ldc, int K, float alpha,
    const float* __restrict__ bias, const float* __restrict__ res,
    long long aO, long long aI, long long bO, long long bI,
    long long cO, long long cI, int innerB)
{
    constexpr int BM = 128, BK = 32;
    constexpr int WN = BN / 4;          // 4 warp-columns
    constexpr int NFRAG = WN / 8;
    constexpr int AST = 36;             // k-major row stride (words)
    constexpr int BST_NN = BN + 8;      // NN B row stride (words)

    int z = blockIdx.z;
    if (innerB > 0) {
        long long zo = z / innerB, zi = z % innerB;
        A  += zo * aO + zi * aI;
        Bm += zo * bO + zi * bI;
        C  += zo * cO + zi * cI;
    }
    int m0 = blockIdx.y * BM;
    int n0 = blockIdx.x * BN;
    int tid = threadIdx.x;
    int warp = tid >> 5, lane = tid & 31;
    int wm = (warp >> 2) * 64;          // 2 warp-rows of 64
    int wn = (warp & 3) * WN;
    int g  = lane >> 2, t4 = lane & 3;

    __shared__ uint32_t As[BM * AST];
    __shared__ uint32_t Bs[BT ? (BN * AST) : (BK * BST_NN)];

    float acc[4][NFRAG][4];
    #pragma unroll
    for (int i = 0; i < 4; i++)
        #pragma unroll
        for (int j = 0; j < NFRAG; j++)
            #pragma unroll
            for (int q = 0; q < 4; q++) acc[i][j][q] = 0.0f;

    for (int k0 = 0; k0 < K; k0 += BK) {
        // ---- load A tile [BM x BK] ----
        #pragma unroll
        for (int it = 0; it < (BM * 8) / 256; it++) {
            int idx = tid + it * 256;
            int r = idx >> 3, c4 = (idx & 7) * 4;
            float4 val = *reinterpret_cast<const float4*>(A + (size_t)(m0 + r) * lda + k0 + c4);
            uint4 pk;
            pk.x = f2tf(val.x); pk.y = f2tf(val.y); pk.z = f2tf(val.z); pk.w = f2tf(val.w);
            *reinterpret_cast<uint4*>(&As[r * AST + c4]) = pk;
        }
        // ---- load B tile ----
        if (BT) {
            #pragma unroll
            for (int it = 0; it < (BN * 8) / 256; it++) {
                int idx = tid + it * 256;
                int r = idx >> 3, c4 = (idx & 7) * 4;
                float4 val = *reinterpret_cast<const float4*>(Bm + (size_t)(n0 + r) * ldb + k0 + c4);
                uint4 pk;
                pk.x = f2tf(val.x); pk.y = f2tf(val.y); pk.z = f2tf(val.z); pk.w = f2tf(val.w);
                *reinterpret_cast<uint4*>(&Bs[r * AST + c4]) = pk;
            }
        } else {
            constexpr int NV = BN / 4;
            #pragma unroll
            for (int it = 0; it < (BK * NV) / 256; it++) {
                int idx = tid + it * 256;
                int r = idx / NV, c4 = (idx % NV) * 4;
                float4 val = *reinterpret_cast<const float4*>(Bm + (size_t)(k0 + r) * ldb + n0 + c4);
                uint4 pk;
                pk.x = f2tf(val.x); pk.y = f2tf(val.y); pk.z = f2tf(val.z); pk.w = f2tf(val.w);
                *reinterpret_cast<uint4*>(&Bs[r * BST_NN + c4]) = pk;
            }
        }
        __syncthreads();

        #pragma unroll
        for (int kk = 0; kk < BK; kk += 8) {
            uint32_t afr[4][4];
            uint32_t bfr[NFRAG][2];
            #pragma unroll
            for (int mf = 0; mf < 4; mf++) {
                int mr = wm + mf * 16 + g;
                afr[mf][0] = As[mr * AST + kk + t4];
                afr[mf][1] = As[(mr + 8) * AST + kk + t4];
                afr[mf][2] = As[mr * AST + kk + t4 + 4];
                afr[mf][3] = As[(mr + 8) * AST + kk + t4 + 4];
            }
            #pragma unroll
            for (int nf = 0; nf < NFRAG; nf++) {
                int n = wn + nf * 8 + g;
                if (BT) {
                    bfr[nf][0] = Bs[n * AST + kk + t4];
                    bfr[nf][1] = Bs[n * AST + kk + t4 + 4];
                } else {
                    bfr[nf][0] = Bs[(kk + t4) * BST_NN + n];
                    bfr[nf][1] = Bs[(kk + t4 + 4) * BST_NN + n];
                }
            }
            #pragma unroll
            for (int mf = 0; mf < 4; mf++)
                #pragma unroll
                for (int nf = 0; nf < NFRAG; nf++)
                    mma8(acc[mf][nf], afr[mf], bfr[nf]);
        }
        __syncthreads();
    }

    // ---- epilogue ----
    #pragma unroll
    for (int mf = 0; mf < 4; mf++) {
        #pragma unroll
        for (int nf = 0; nf < NFRAG; nf++) {
            #pragma unroll
            for (int i = 0; i < 4; i++) {
                int m = m0 + wm + mf * 16 + g + ((i >= 2) ? 8 : 0);
                int n = n0 + wn + nf * 8 + t4 * 2 + (i & 1);
                float v = acc[mf][nf][i] * alpha;
                if (EPI >= 1) v += bias[n];
                if (EPI == 2) v += res[(size_t)m * ldc + n];
                if (EPI == 3) v = gelu_exact(v);
                C[(size_t)m * ldc + n] = v;
            }
        }
    }
}

// ------------------- host launch -------------------
static float* sym_addr(const void* symbol) {
    void* p = nullptr;
    cudaGetSymbolAddress(&p, symbol);
    return reinterpret_cast<float*>(p);
}

extern "C" void kernel_launch(void* const* d_in, const int* in_sizes, int n_in,
                              void* d_out, int out_size) {
    (void)in_sizes; (void)n_in; (void)out_size;
    const float* value = (const float*)d_in[0];
    const float* key   = (const float*)d_in[1];
    const float* query = (const float*)d_in[2];
    const int*   mask  = (const int*)  d_in[3];
    const float* Wv    = (const float*)d_in[4];
    const float* Wk    = (const float*)d_in[5];
    const float* Wq    = (const float*)d_in[6];
    const float* Wo    = (const float*)d_in[7];
    const float* bo    = (const float*)d_in[8];
    const float* ln1_g = (const float*)d_in[9];
    const float* ln1_b = (const float*)d_in[10];
    const float* ln2_g = (const float*)d_in[11];
    const float* ln2_b = (const float*)d_in[12];
    const float* lnf_g = (const float*)d_in[13];
    const float* lnf_b = (const float*)d_in[14];
    const float* W1    = (const float*)d_in[15];
    const float* b1    = (const float*)d_in[16];
    const float* W2    = (const float*)d_in[17];
    const float* b2    = (const float*)d_in[18];
    float* out = (float*)d_out;

    float* p_qln = sym_addr(g_qln);
    float* p_vln = sym_addr(g_vln);
    float* p_kln = sym_addr(g_kln);
    float* p_Q   = sym_addr(g_Q);
    float* p_K   = sym_addr(g_K);
    float* p_V   = sym_addr(g_V);
    float* p_sc  = sym_addr(g_scores);
    float* p_att = sym_addr(g_att);
    float* p_x   = sym_addr(g_x);
    float* p_h   = sym_addr(g_h);
    float* p_ff  = sym_addr(g_ff);

    // 1) pre-norms
    ln_kernel<<<NTOK, 256>>>(query, p_qln, ln1_g, ln1_b);
    ln_kernel<<<NTOK, 256>>>(value, p_vln, ln2_g, ln2_b);
    ln_kernel<<<NTOK, 256>>>(key,   p_kln, ln2_g, ln2_b);

    // 2) QKV projections
    dim3 gProj(EDIM / 128, NTOK / 128, 1);
    gemm_tf32<128, false, 0><<<gProj, 256>>>(p_qln, Wq, p_Q, EDIM, EDIM, EDIM, EDIM,
        1.0f, nullptr, nullptr, 0, 0, 0, 0, 0, 0, 0);
    gemm_tf32<128, false, 0><<<gProj, 256>>>(p_kln, Wk, p_K, EDIM, EDIM, EDIM, EDIM,
        1.0f, nullptr, nullptr, 0, 0, 0, 0, 0, 0, 0);
    gemm_tf32<128, false, 0><<<gProj, 256>>>(p_vln, Wv, p_V, EDIM, EDIM, EDIM, EDIM,
        1.0f, nullptr, nullptr, 0, 0, 0, 0, 0, 0, 0);

    // 3) energy = (Q @ K^T) / 8, batched per (b,h)
    dim3 gQK(SEQ / 128, SEQ / 128, BATCH * NHEAD);
    gemm_tf32<128, true, 0><<<gQK, 256>>>(p_Q, p_K, p_sc, EDIM, EDIM, SEQ, HDIM,
        0.125f, nullptr, nullptr,
        (long long)SEQ * EDIM, HDIM,
        (long long)SEQ * EDIM, HDIM,
        (long long)NHEAD * SEQ * SEQ, (long long)SEQ * SEQ, NHEAD);

    // 4) masked softmax
    softmax_kernel<<<BATCH * NHEAD * SEQ, 256>>>(p_sc, mask);

    // 5) out = attn @ V, batched per (b,h)
    dim3 gAV(1, SEQ / 128, BATCH * NHEAD);
    gemm_tf32<64, false, 0><<<gAV, 256>>>(p_sc, p_V, p_att, SEQ, EDIM, EDIM, SEQ,
        1.0f, nullptr, nullptr,
        (long long)NHEAD * SEQ * SEQ, (long long)SEQ * SEQ,
        (long long)SEQ * EDIM, HDIM,
        (long long)SEQ * EDIM, HDIM, NHEAD);

    // 6) x = att @ Wo + bo + q_ln
    gemm_tf32<128, false, 2><<<gProj, 256>>>(p_att, Wo, p_x, EDIM, EDIM, EDIM, EDIM,
        1.0f, bo, p_qln, 0, 0, 0, 0, 0, 0, 0);

    // 7) h = LN_f(x)
    ln_kernel<<<NTOK, 256>>>(p_x, p_h, lnf_g, lnf_b);

    // 8) ff = gelu(h @ W1 + b1)
    dim3 gF1(FFDIM / 128, NTOK / 128, 1);
    gemm_tf32<128, false, 3><<<gF1, 256>>>(p_h, W1, p_ff, EDIM, FFDIM, FFDIM, EDIM,
        1.0f, b1, nullptr, 0, 0, 0, 0, 0, 0, 0);

    // 9) out = ff @ W2 + b2 + x
    dim3 gF2(EDIM / 128, NTOK / 128, 1);
    gemm_tf32<128, false, 2><<<gF2, 256>>>(p_ff, W2, out, FFDIM, EDIM, EDIM, FFDIM,
        1.0f, b2, p_x, 0, 0, 0, 0, 0, 0, 0);
}

// round 4
// speedup vs baseline: 1.7963x; 1.0230x over previous
#include <cuda_runtime.h>
#include <cstdint>
#include <cstddef>

#define EDIM 1024
#define NHEAD 16
#define HDIM 64
#define FFDIM 4096
#define BATCH 4
#define SEQ 2048
#define NTOK (BATCH*SEQ)   // 8192

// ------------------- scratch (device globals; no allocations) -------------------
__device__ float g_qln[(size_t)NTOK*EDIM];
__device__ float g_vln[(size_t)NTOK*EDIM];
__device__ float g_kln[(size_t)NTOK*EDIM];
__device__ float g_Q  [(size_t)NTOK*EDIM];
__device__ float g_K  [(size_t)NTOK*EDIM];
__device__ float g_V  [(size_t)NTOK*EDIM];
__device__ float g_att[(size_t)NTOK*EDIM];
__device__ float g_x  [(size_t)NTOK*EDIM];
__device__ float g_h  [(size_t)NTOK*EDIM];
__device__ float g_ff [(size_t)NTOK*FFDIM];

// ------------------- helpers -------------------
__device__ __forceinline__ uint32_t f2tf(float f) {
    uint32_t u;
    asm("cvt.rna.tf32.f32 %0, %1;" : "=r"(u) : "f"(f));
    return u;
}

__device__ __forceinline__ void mma8(float* c, const uint32_t* a, const uint32_t* b) {
    asm volatile(
        "mma.sync.aligned.m16n8k8.row.col.f32.tf32.tf32.f32 "
        "{%0,%1,%2,%3},{%4,%5,%6,%7},{%8,%9},{%0,%1,%2,%3};\n"
        : "+f"(c[0]), "+f"(c[1]), "+f"(c[2]), "+f"(c[3])
        : "r"(a[0]), "r"(a[1]), "r"(a[2]), "r"(a[3]), "r"(b[0]), "r"(b[1]));
}

__device__ __forceinline__ float gelu_exact(float v) {
    return 0.5f * v * (1.0f + erff(v * 0.70710678118654752f));
}

#define CP16(dst_sm, src_g) \
    asm volatile("cp.async.cg.shared.global [%0], [%1], 16;\n" :: \
        "r"((uint32_t)__cvta_generic_to_shared(dst_sm)), "l"(src_g))
#define CP_COMMIT() asm volatile("cp.async.commit_group;\n")
#define CP_WAIT1()  asm volatile("cp.async.wait_group 1;\n")
#define CP_WAIT0()  asm volatile("cp.async.wait_group 0;\n")

// ------------------- LayerNorm -------------------
__global__ __launch_bounds__(256) void ln_kernel(
    const float* __restrict__ in, float* __restrict__ out,
    const float* __restrict__ gw, const float* __restrict__ gb)
{
    int row = blockIdx.x;
    int tid = threadIdx.x;
    const float4* inr = reinterpret_cast<const float4*>(in + (size_t)row * EDIM);
    float4 v = inr[tid];
    float s  = v.x + v.y + v.z + v.w;
    float sq = v.x*v.x + v.y*v.y + v.z*v.z + v.w*v.w;

    int lane = tid & 31, warp = tid >> 5;
    #pragma unroll
    for (int o = 16; o > 0; o >>= 1) {
        s  += __shfl_xor_sync(0xffffffffu, s, o);
        sq += __shfl_xor_sync(0xffffffffu, sq, o);
    }
    __shared__ float rs[8], rq[8];
    if (lane == 0) { rs[warp] = s; rq[warp] = sq; }
    __syncthreads();
    if (warp == 0) {
        float s2 = (lane < 8) ? rs[lane] : 0.0f;
        float q2 = (lane < 8) ? rq[lane] : 0.0f;
        #pragma unroll
        for (int o = 4; o > 0; o >>= 1) {
            s2 += __shfl_xor_sync(0xffffffffu, s2, o);
            q2 += __shfl_xor_sync(0xffffffffu, q2, o);
        }
        if (lane == 0) { rs[0] = s2; rq[0] = q2; }
    }
    __syncthreads();
    float mean = rs[0] * (1.0f / EDIM);
    float var  = rq[0] * (1.0f / EDIM) - mean * mean;
    float rstd = rsqrtf(var + 1e-5f);

    float4 gg = reinterpret_cast<const float4*>(gw)[tid];
    float4 bb = reinterpret_cast<const float4*>(gb)[tid];
    float4 o4;
    o4.x = (v.x - mean) * rstd * gg.x + bb.x;
    o4.y = (v.y - mean) * rstd * gg.y + bb.y;
    o4.z = (v.z - mean) * rstd * gg.z + bb.z;
    o4.w = (v.w - mean) * rstd * gg.w + bb.w;
    reinterpret_cast<float4*>(out + (size_t)row * EDIM)[tid] = o4;
}

// ------------------- flash attention (tf32 mma, online softmax) -------------------
// grid: (qtile=16, h=16, b=4), 256 threads.
// BR=128 q rows per CTA, BC=64 kv per chunk, HD=64.
// smem word layout (k-major tiles need stride >= 64; 68 keeps banks bijective):
//   Qs   [0,      8704)   128 x 68   (tf32, Q*0.125)
//   Ss   [8704,  17408)   128 x 68   (S fp32, then P tf32 in place)
//   Ks   [17408, 26112)   2 x 64x68  (raw fp32, cp.async double buffer)
//   Vs   [26112, 35328)   2 x 64x72  (raw fp32)
//   cf   [35328, 35456)   128
//   ls   [35456, 35584)   128
//   mk   [35584, 35648)   64 ints
#define FLASH_SMEM_WORDS 35648

__global__ __launch_bounds__(256) void flash_kernel(
    const float* __restrict__ Qg, const float* __restrict__ Kg,
    const float* __restrict__ Vg, const int* __restrict__ mask,
    float* __restrict__ Og)
{
    extern __shared__ float sm[];
    float*    Qs   = sm;
    float*    Ss   = sm + 8704;
    float*    Ks   = sm + 17408;
    float*    Vs   = sm + 26112;
    float*    cf_s = sm + 35328;
    float*    l_s  = sm + 35456;
    int*      mk_s = (int*)(sm + 35584);
    uint32_t* Qsu  = (uint32_t*)Qs;
    uint32_t* Ssu  = (uint32_t*)Ss;

    int qt = blockIdx.x, h = blockIdx.y, b = blockIdx.z;
    int tokbase = b * SEQ + qt * 128;
    const float* Qb = Qg + (size_t)tokbase * EDIM + h * HDIM;
    const float* Kb0 = Kg + (size_t)b * SEQ * EDIM + h * HDIM;
    const float* Vb0 = Vg + (size_t)b * SEQ * EDIM + h * HDIM;
    const int* mrow = mask + (size_t)b * SEQ;

    int tid = threadIdx.x, warp = tid >> 5, lane = tid & 31;
    int wm = (warp >> 1) * 32;     // 4 m-bands of 32
    int wn = (warp & 1) * 32;      // 2 n-bands of 32
    int g = lane >> 2, t4 = lane & 3;

    // preload Q tile, fold 1/sqrt(HD)=0.125 scale, convert to tf32
    #pragma unroll
    for (int it = 0; it < 8; it++) {
        int idx = tid + it * 256;
        int r = idx >> 4, c4 = (idx & 15) * 4;
        float4 v = *reinterpret_cast<const float4*>(Qb + (size_t)r * EDIM + c4);
        uint4 pk;
        pk.x = f2tf(v.x * 0.125f); pk.y = f2tf(v.y * 0.125f);
        pk.z = f2tf(v.z * 0.125f); pk.w = f2tf(v.w * 0.125f);
        *reinterpret_cast<uint4*>(&Qsu[r * 68 + c4]) = pk;
    }

    auto issue_kv = [&](int j, int buf) {
        const float* Kc = Kb0 + (size_t)j * 64 * EDIM;
        const float* Vc = Vb0 + (size_t)j * 64 * EDIM;
        float* Kd = Ks + buf * 4352;
        float* Vd = Vs + buf * 4608;
        #pragma unroll
        for (int it = 0; it < 4; it++) {
            int idx = tid + it * 256;
            int r = idx >> 4, c4 = (idx & 15) * 4;
            CP16(&Kd[r * 68 + c4], Kc + (size_t)r * EDIM + c4);
        }
        #pragma unroll
        for (int it = 0; it < 4; it++) {
            int idx = tid + it * 256;
            int r = idx >> 4, c4 = (idx & 15) * 4;
            CP16(&Vd[r * 72 + c4], Vc + (size_t)r * EDIM + c4);
        }
    };

    issue_kv(0, 0);
    CP_COMMIT();

    float m_reg = -1e30f, l_reg = 0.0f;   // row stats (threads < 128)
    float oacc[2][4][4];
    #pragma unroll
    for (int a = 0; a < 2; a++)
        #pragma unroll
        for (int c = 0; c < 4; c++)
            #pragma unroll
            for (int i = 0; i < 4; i++) oacc[a][c][i] = 0.0f;

    const int NCH = SEQ / 64;
    for (int j = 0; j < NCH; j++) {
        int buf = j & 1;
        if (j + 1 < NCH) { issue_kv(j + 1, buf ^ 1); CP_COMMIT(); CP_WAIT1(); }
        else             { CP_WAIT0(); }
        __syncthreads();                     // K/V chunk j (and Q on iter 0) visible

        // ---- S = (Q*0.125) @ K^T ----
        const float* Kb = Ks + buf * 4352;
        float sacc[2][4][4];
        #pragma unroll
        for (int a = 0; a < 2; a++)
            #pragma unroll
            for (int c = 0; c < 4; c++)
                #pragma unroll
                for (int i = 0; i < 4; i++) sacc[a][c][i] = 0.0f;

        #pragma unroll
        for (int kk = 0; kk < 64; kk += 8) {
            uint32_t afr[2][4], bfr[4][2];
            #pragma unroll
            for (int mf = 0; mf < 2; mf++) {
                int mr = wm + mf * 16 + g;
                afr[mf][0] = Qsu[mr * 68 + kk + t4];
                afr[mf][1] = Qsu[(mr + 8) * 68 + kk + t4];
                afr[mf][2] = Qsu[mr * 68 + kk + t4 + 4];
                afr[mf][3] = Qsu[(mr + 8) * 68 + kk + t4 + 4];
            }
            #pragma unroll
            for (int nf = 0; nf < 4; nf++) {
                int n = wn + nf * 8 + g;
                bfr[nf][0] = f2tf(Kb[n * 68 + kk + t4]);
                bfr[nf][1] = f2tf(Kb[n * 68 + kk + t4 + 4]);
            }
            #pragma unroll
            for (int mf = 0; mf < 2; mf++)
                #pragma unroll
                for (int nf = 0; nf < 4; nf++)
                    mma8(sacc[mf][nf], afr[mf], bfr[nf]);
        }

        // store S tile; load mask chunk
        #pragma unroll
        for (int mf = 0; mf < 2; mf++) {
            #pragma unroll
            for (int nf = 0; nf < 4; nf++) {
                int r0 = wm + mf * 16 + g;
                int c0 = wn + nf * 8 + 2 * t4;
                Ss[r0 * 68 + c0]           = sacc[mf][nf][0];
                Ss[r0 * 68 + c0 + 1]       = sacc[mf][nf][1];
                Ss[(r0 + 8) * 68 + c0]     = sacc[mf][nf][2];
                Ss[(r0 + 8) * 68 + c0 + 1] = sacc[mf][nf][3];
            }
        }
        if (tid < 64) mk_s[tid] = mrow[j * 64 + tid];
        __syncthreads();

        // ---- online softmax row pass (threads 0..127, row = tid) ----
        if (tid < 128) {
            int r = tid;
            float mx = -1e30f;
            #pragma unroll 8
            for (int cc = 0; cc < 64; cc++) {
                int c = (r + cc) & 63;       // staggered -> conflict-free
                float s = Ss[r * 68 + c];
                if (mk_s[c] == 0) s = -1e20f;
                mx = fmaxf(mx, s);
            }
            float m_new = fmaxf(m_reg, mx);
            float corr = __expf(m_reg - m_new);
            float sum = 0.0f;
            #pragma unroll 8
            for (int cc = 0; cc < 64; cc++) {
                int c = (r + cc) & 63;
                float s = Ss[r * 68 + c];
                if (mk_s[c] == 0) s = -1e20f;
                float p = __expf(s - m_new);
                sum += p;
                Ssu[r * 68 + c] = f2tf(p);   // overwrite as tf32 P
            }
            l_reg = l_reg * corr + sum;
            m_reg = m_new;
            cf_s[r] = corr;
        }
        __syncthreads();

        // ---- rescale O, accumulate P @ V ----
        const float* Vb = Vs + buf * 4608;
        #pragma unroll
        for (int mf = 0; mf < 2; mf++) {
            float cg  = cf_s[wm + mf * 16 + g];
            float cg8 = cf_s[wm + mf * 16 + g + 8];
            #pragma unroll
            for (int nf = 0; nf < 4; nf++) {
                oacc[mf][nf][0] *= cg;  oacc[mf][nf][1] *= cg;
                oacc[mf][nf][2] *= cg8; oacc[mf][nf][3] *= cg8;
            }
        }
        #pragma unroll
        for (int kk = 0; kk < 64; kk += 8) {
            uint32_t afr[2][4], bfr[4][2];
            #pragma unroll
            for (int mf = 0; mf < 2; mf++) {
                int mr = wm + mf * 16 + g;
                afr[mf][0] = Ssu[mr * 68 + kk + t4];
                afr[mf][1] = Ssu[(mr + 8) * 68 + kk + t4];
                afr[mf][2] = Ssu[mr * 68 + kk + t4 + 4];
                afr[mf][3] = Ssu[(mr + 8) * 68 + kk + t4 + 4];
            }
            #pragma unroll
            for (int nf = 0; nf < 4; nf++) {
                int n = wn + nf * 8 + g;
                bfr[nf][0] = f2tf(Vb[(kk + t4) * 72 + n]);
                bfr[nf][1] = f2tf(Vb[(kk + t4 + 4) * 72 + n]);
            }
            #pragma unroll
            for (int mf = 0; mf < 2; mf++)
                #pragma unroll
                for (int nf = 0; nf < 4; nf++)
                    mma8(oacc[mf][nf], afr[mf], bfr[nf]);
        }
        __syncthreads();   // protect Ss + K/V buffers before next chunk
    }

    if (tid < 128) l_s[tid] = l_reg;
    __syncthreads();

    float* Ob = Og + (size_t)tokbase * EDIM + h * HDIM;
    #pragma unroll
    for (int mf = 0; mf < 2; mf++) {
        #pragma unroll
        for (int nf = 0; nf < 4; nf++) {
            int r0 = wm + mf * 16 + g;
            int c0 = wn + nf * 8 + 2 * t4;
            float inv0 = 1.0f / l_s[r0];
            float inv8 = 1.0f / l_s[r0 + 8];
            Ob[(size_t)r0 * EDIM + c0]           = oacc[mf][nf][0] * inv0;
            Ob[(size_t)r0 * EDIM + c0 + 1]       = oacc[mf][nf][1] * inv0;
            Ob[(size_t)(r0 + 8) * EDIM + c0]     = oacc[mf][nf][2] * inv8;
            Ob[(size_t)(r0 + 8) * EDIM + c0 + 1] = oacc[mf][nf][3] * inv8;
        }
    }
}

// ------------------- NN tf32 GEMM, 3-stage cp.async pipeline -------------------
// C[M,N] = A[M,K] @ B[K,N] (+ epilogue). BM=128, BN=128, BK=32.
// EPI: 0 none, 2 +bias+res, 3 gelu(acc+bias)
// smem: As 3 x 128x36 raw fp32, Bs 3 x 32x136 raw fp32.
#define GEMM_SMEM_WORDS (3*4608 + 3*4352)

template<int EPI>
__global__ __launch_bounds__(256) void gemm_nn(
    const float* __restrict__ A, const float* __restrict__ Bm, float* __restrict__ C,
    int K, int N,
    const float* __restrict__ bias, const float* __restrict__ res)
{
    extern __shared__ float smf[];
    float* As = smf;
    float* Bs = smf + 3 * 4608;

    int m0 = blockIdx.y * 128, n0 = blockIdx.x * 128;
    int tid = threadIdx.x, warp = tid >> 5, lane = tid & 31;
    int wm = (warp >> 2) * 64, wn = (warp & 3) * 32;
    int g = lane >> 2, t4 = lane & 3;

    const int T = K >> 5;

    auto issue = [&](int t) {
        int s = t % 3;
        int k0 = t << 5;
        float* Ad = As + s * 4608;
        float* Bd = Bs + s * 4352;
        #pragma unroll
        for (int it = 0; it < 4; it++) {
            int idx = tid + it * 256;
            int r = idx >> 3, c4 = (idx & 7) * 4;
            CP16(&Ad[r * 36 + c4], A + (size_t)(m0 + r) * K + k0 + c4);
        }
        #pragma unroll
        for (int it = 0; it < 4; it++) {
            int idx = tid + it * 256;
            int r = idx >> 5, c4 = (idx & 31) * 4;
            CP16(&Bd[r * 136 + c4], Bm + (size_t)(k0 + r) * N + n0 + c4);
        }
    };

    float acc[4][4][4];
    #pragma unroll
    for (int a = 0; a < 4; a++)
        #pragma unroll
        for (int c = 0; c < 4; c++)
            #pragma unroll
            for (int i = 0; i < 4; i++) acc[a][c][i] = 0.0f;

    issue(0);
    CP_COMMIT();

    for (int t = 0; t < T; t++) {
        if (t + 1 < T) { issue(t + 1); CP_COMMIT(); CP_WAIT1(); }
        else           { CP_WAIT0(); }
        __syncthreads();

        const float* Af = As + (t % 3) * 4608;
        const float* Bf = Bs + (t % 3) * 4352;
        #pragma unroll
        for (int kk = 0; kk < 32; kk += 8) {
            uint32_t afr[4][4], bfr[4][2];
            #pragma unroll
            for (int mf = 0; mf < 4; mf++) {
                int mr = wm + mf * 16 + g;
                afr[mf][0] = f2tf(Af[mr * 36 + kk + t4]);
                afr[mf][1] = f2tf(Af[(mr + 8) * 36 + kk + t4]);
                afr[mf][2] = f2tf(Af[mr * 36 + kk + t4 + 4]);
                afr[mf][3] = f2tf(Af[(mr + 8) * 36 + kk + t4 + 4]);
            }
            #pragma unroll
            for (int nf = 0; nf < 4; nf++) {
                int n = wn + nf * 8 + g;
                bfr[nf][0] = f2tf(Bf[(kk + t4) * 136 + n]);
                bfr[nf][1] = f2tf(Bf[(kk + t4 + 4) * 136 + n]);
            }
            #pragma unroll
            for (int mf = 0; mf < 4; mf++)
                #pragma unroll
                for (int nf = 0; nf < 4; nf++)
                    mma8(acc[mf][nf], afr[mf], bfr[nf]);
        }
    }

    #pragma unroll
    for (int mf = 0; mf < 4; mf++) {
        #pragma unroll
        for (int nf = 0; nf < 4; nf++) {
            #pragma unroll
            for (int i = 0; i < 4; i++) {
                int m = m0 + wm + mf * 16 + g + ((i >= 2) ? 8 : 0);
                int n = n0 + wn + nf * 8 + 2 * t4 + (i & 1);
                float v = acc[mf][nf][i];
                if (EPI >= 1) v += bias[n];
                if (EPI == 2) v += res[(size_t)m * N + n];
                if (EPI == 3) v = gelu_exact(v);
                C[(size_t)m * N + n] = v;
            }
        }
    }
}

// ------------------- host launch -------------------
static float* sym_addr(const void* symbol) {
    void* p = nullptr;
    cudaGetSymbolAddress(&p, symbol);
    return reinterpret_cast<float*>(p);
}

extern "C" void kernel_launch(void* const* d_in, const int* in_sizes, int n_in,
                              void* d_out, int out_size) {
    (void)in_sizes; (void)n_in; (void)out_size;
    const float* value = (const float*)d_in[0];
    const float* key   = (const float*)d_in[1];
    const float* query = (const float*)d_in[2];
    const int*   mask  = (const int*)  d_in[3];
    const float* Wv    = (const float*)d_in[4];
    const float* Wk    = (const float*)d_in[5];
    const float* Wq    = (const float*)d_in[6];
    const float* Wo    = (const float*)d_in[7];
    const float* bo    = (const float*)d_in[8];
    const float* ln1_g = (const float*)d_in[9];
    const float* ln1_b = (const float*)d_in[10];
    const float* ln2_g = (const float*)d_in[11];
    const float* ln2_b = (const float*)d_in[12];
    const float* lnf_g = (const float*)d_in[13];
    const float* lnf_b = (const float*)d_in[14];
    const float* W1    = (const float*)d_in[15];
    const float* b1    = (const float*)d_in[16];
    const float* W2    = (const float*)d_in[17];
    const float* b2    = (const float*)d_in[18];
    float* out = (float*)d_out;

    float* p_qln = sym_addr(g_qln);
    float* p_vln = sym_addr(g_vln);
    float* p_kln = sym_addr(g_kln);
    float* p_Q   = sym_addr(g_Q);
    float* p_K   = sym_addr(g_K);
    float* p_V   = sym_addr(g_V);
    float* p_att = sym_addr(g_att);
    float* p_x   = sym_addr(g_x);
    float* p_h   = sym_addr(g_h);
    float* p_ff  = sym_addr(g_ff);

    const int GSM = GEMM_SMEM_WORDS * 4;     // 107520
    const int FSM = FLASH_SMEM_WORDS * 4;    // 142592
    cudaFuncSetAttribute(gemm_nn<0>, cudaFuncAttributeMaxDynamicSharedMemorySize, GSM);
    cudaFuncSetAttribute(gemm_nn<2>, cudaFuncAttributeMaxDynamicSharedMemorySize, GSM);
    cudaFuncSetAttribute(gemm_nn<3>, cudaFuncAttributeMaxDynamicSharedMemorySize, GSM);
    cudaFuncSetAttribute(flash_kernel, cudaFuncAttributeMaxDynamicSharedMemorySize, FSM);

    // 1) pre-norms
    ln_kernel<<<NTOK, 256>>>(query, p_qln, ln1_g, ln1_b);
    ln_kernel<<<NTOK, 256>>>(value, p_vln, ln2_g, ln2_b);
    ln_kernel<<<NTOK, 256>>>(key,   p_kln, ln2_g, ln2_b);

    // 2) QKV projections
    dim3 gProj(EDIM / 128, NTOK / 128, 1);
    gemm_nn<0><<<gProj, 256, GSM>>>(p_qln, Wq, p_Q, EDIM, EDIM, nullptr, nullptr);
    gemm_nn<0><<<gProj, 256, GSM>>>(p_kln, Wk, p_K, EDIM, EDIM, nullptr, nullptr);
    gemm_nn<0><<<gProj, 256, GSM>>>(p_vln, Wv, p_V, EDIM, EDIM, nullptr, nullptr);

    // 3) fused attention
    dim3 gF(SEQ / 128, NHEAD, BATCH);
    flash_kernel<<<gF, 256, FSM>>>(p_Q, p_K, p_V, mask, p_att);

    // 4) x = att @ Wo + bo + q_ln
    gemm_nn<2><<<gProj, 256, GSM>>>(p_att, Wo, p_x, EDIM, EDIM, bo, p_qln);

    // 5) h = LN_f(x)
    ln_kernel<<<NTOK, 256>>>(p_x, p_h, lnf_g, lnf_b);

    // 6) ff = gelu(h @ W1 + b1)
    dim3 gF1(FFDIM / 128, NTOK / 128, 1);
    gemm_nn<3><<<gF1, 256, GSM>>>(p_h, W1, p_ff, EDIM, FFDIM, b1, nullptr);

    // 7) out = ff @ W2 + b2 + x
    dim3 gF2(EDIM / 128, NTOK / 128, 1);
    gemm_nn<2><<<gF2, 256, GSM>>>(p_ff, W2, out, FFDIM, EDIM, b2, p_x);
}

// round 5
// speedup vs baseline: 2.5673x; 1.4292x over previous
#include <cuda_runtime.h>
#include <cstdint>
#include <cstddef>

#define EDIM 1024
#define NHEAD 16
#define HDIM 64
#define FFDIM 4096
#define BATCH 4
#define SEQ 2048
#define NTOK (BATCH*SEQ)   // 8192

// ------------------- scratch (device globals; no allocations) -------------------
__device__ float g_qln[(size_t)NTOK*EDIM];
__device__ float g_vln[(size_t)NTOK*EDIM];
__device__ float g_kln[(size_t)NTOK*EDIM];
__device__ float g_Q  [(size_t)NTOK*EDIM];
__device__ float g_K  [(size_t)NTOK*EDIM];
__device__ float g_V  [(size_t)NTOK*EDIM];
__device__ float g_att[(size_t)NTOK*EDIM];
__device__ float g_x  [(size_t)NTOK*EDIM];
__device__ float g_h  [(size_t)NTOK*EDIM];
__device__ float g_ff [(size_t)NTOK*FFDIM];
__device__ float g_maskf[(size_t)BATCH*SEQ];

// ------------------- helpers -------------------
__device__ __forceinline__ uint32_t f2tf(float f) {
    uint32_t u;
    asm("cvt.rna.tf32.f32 %0, %1;" : "=r"(u) : "f"(f));
    return u;
}

__device__ __forceinline__ void mma8(float* c, const uint32_t* a, const uint32_t* b) {
    asm volatile(
        "mma.sync.aligned.m16n8k8.row.col.f32.tf32.tf32.f32 "
        "{%0,%1,%2,%3},{%4,%5,%6,%7},{%8,%9},{%0,%1,%2,%3};\n"
        : "+f"(c[0]), "+f"(c[1]), "+f"(c[2]), "+f"(c[3])
        : "r"(a[0]), "r"(a[1]), "r"(a[2]), "r"(a[3]), "r"(b[0]), "r"(b[1]));
}

__device__ __forceinline__ float gelu_exact(float v) {
    return 0.5f * v * (1.0f + erff(v * 0.70710678118654752f));
}

#define CP16(dst_sm, src_g) \
    asm volatile("cp.async.cg.shared.global [%0], [%1], 16;\n" :: \
        "r"((uint32_t)__cvta_generic_to_shared(dst_sm)), "l"(src_g))
#define CP_COMMIT() asm volatile("cp.async.commit_group;\n")
#define CP_WAIT1()  asm volatile("cp.async.wait_group 1;\n")
#define CP_WAIT0()  asm volatile("cp.async.wait_group 0;\n")

// ------------------- mask -> float addend -------------------
__global__ __launch_bounds__(256) void maskf_kernel(
    const int* __restrict__ mask, float* __restrict__ mf)
{
    int i = blockIdx.x * 256 + threadIdx.x;
    mf[i] = (mask[i] == 0) ? -1e20f : 0.0f;
}

// ------------------- LayerNorm -------------------
__global__ __launch_bounds__(256) void ln_kernel(
    const float* __restrict__ in, float* __restrict__ out,
    const float* __restrict__ gw, const float* __restrict__ gb)
{
    int row = blockIdx.x;
    int tid = threadIdx.x;
    const float4* inr = reinterpret_cast<const float4*>(in + (size_t)row * EDIM);
    float4 v = inr[tid];
    float s  = v.x + v.y + v.z + v.w;
    float sq = v.x*v.x + v.y*v.y + v.z*v.z + v.w*v.w;

    int lane = tid & 31, warp = tid >> 5;
    #pragma unroll
    for (int o = 16; o > 0; o >>= 1) {
        s  += __shfl_xor_sync(0xffffffffu, s, o);
        sq += __shfl_xor_sync(0xffffffffu, sq, o);
    }
    __shared__ float rs[8], rq[8];
    if (lane == 0) { rs[warp] = s; rq[warp] = sq; }
    __syncthreads();
    if (warp == 0) {
        float s2 = (lane < 8) ? rs[lane] : 0.0f;
        float q2 = (lane < 8) ? rq[lane] : 0.0f;
        #pragma unroll
        for (int o = 4; o > 0; o >>= 1) {
            s2 += __shfl_xor_sync(0xffffffffu, s2, o);
            q2 += __shfl_xor_sync(0xffffffffu, q2, o);
        }
        if (lane == 0) { rs[0] = s2; rq[0] = q2; }
    }
    __syncthreads();
    float mean = rs[0] * (1.0f / EDIM);
    float var  = rq[0] * (1.0f / EDIM) - mean * mean;
    float rstd = rsqrtf(var + 1e-5f);

    float4 gg = reinterpret_cast<const float4*>(gw)[tid];
    float4 bb = reinterpret_cast<const float4*>(gb)[tid];
    float4 o4;
    o4.x = (v.x - mean) * rstd * gg.x + bb.x;
    o4.y = (v.y - mean) * rstd * gg.y + bb.y;
    o4.z = (v.z - mean) * rstd * gg.z + bb.z;
    o4.w = (v.w - mean) * rstd * gg.w + bb.w;
    reinterpret_cast<float4*>(out + (size_t)row * EDIM)[tid] = o4;
}

// ------------------- flash attention v2 (register softmax) -------------------
// grid (qtile=16, h=16, b=4), 256 threads, 2 CTAs/SM.
// Warp tile: 16 q-rows x 64 kv-cols; 8 warps cover 128 q-rows.
// smem words: Qs [0,8704) 128x68 tf32(Q*0.125); Ks [8704,17408) 2x64x68 raw;
//             Vs [17408,26624) 2x64x72 raw.
#define FLASH_SMEM_WORDS 26624

__global__ __launch_bounds__(256, 2) void flash_kernel(
    const float* __restrict__ Qg, const float* __restrict__ Kg,
    const float* __restrict__ Vg, const float* __restrict__ maskf,
    float* __restrict__ Og)
{
    extern __shared__ float sm[];
    float*    Qs = sm;
    float*    Ks = sm + 8704;
    float*    Vs = sm + 17408;
    uint32_t* Qsu = (uint32_t*)Qs;

    int qt = blockIdx.x, h = blockIdx.y, b = blockIdx.z;
    int tokbase = b * SEQ + qt * 128;
    const float* Qb  = Qg + (size_t)tokbase * EDIM + h * HDIM;
    const float* Kb0 = Kg + (size_t)b * SEQ * EDIM + h * HDIM;
    const float* Vb0 = Vg + (size_t)b * SEQ * EDIM + h * HDIM;
    const float* mfb = maskf + (size_t)b * SEQ;

    int tid = threadIdx.x, w = tid >> 5, lane = tid & 31;
    int g = lane >> 2, t4 = lane & 3;
    int r0 = w * 16 + g;               // first owned row; second is r0+8
    int lo = lane & ~3;

    // stage Q tile (fold 0.125, convert tf32), stride 68 (conflict-free frags)
    #pragma unroll
    for (int it = 0; it < 8; it++) {
        int idx = tid + it * 256;
        int r = idx >> 4, c4 = (idx & 15) * 4;
        float4 v = *reinterpret_cast<const float4*>(Qb + (size_t)r * EDIM + c4);
        uint4 pk;
        pk.x = f2tf(v.x * 0.125f); pk.y = f2tf(v.y * 0.125f);
        pk.z = f2tf(v.z * 0.125f); pk.w = f2tf(v.w * 0.125f);
        *reinterpret_cast<uint4*>(&Qsu[r * 68 + c4]) = pk;
    }

    auto issue_kv = [&](int j, int buf) {
        const float* Kc = Kb0 + (size_t)j * 64 * EDIM;
        const float* Vc = Vb0 + (size_t)j * 64 * EDIM;
        float* Kd = Ks + buf * 4352;
        float* Vd = Vs + buf * 4608;
        #pragma unroll
        for (int it = 0; it < 4; it++) {
            int idx = tid + it * 256;
            int r = idx >> 4, c4 = (idx & 15) * 4;
            CP16(&Kd[r * 68 + c4], Kc + (size_t)r * EDIM + c4);
        }
        #pragma unroll
        for (int it = 0; it < 4; it++) {
            int idx = tid + it * 256;
            int r = idx >> 4, c4 = (idx & 15) * 4;
            CP16(&Vd[r * 72 + c4], Vc + (size_t)r * EDIM + c4);
        }
    };

    issue_kv(0, 0);
    CP_COMMIT();

    float m0 = -1e30f, m1 = -1e30f, l0 = 0.0f, l1 = 0.0f;
    float oacc[8][4];
    #pragma unroll
    for (int nf = 0; nf < 8; nf++)
        #pragma unroll
        for (int i = 0; i < 4; i++) oacc[nf][i] = 0.0f;

    const int NCH = SEQ / 64;
    for (int j = 0; j < NCH; j++) {
        int buf = j & 1;
        if (j + 1 < NCH) { issue_kv(j + 1, buf ^ 1); CP_COMMIT(); CP_WAIT1(); }
        else             { CP_WAIT0(); }
        __syncthreads();

        const float* Kb = Ks + buf * 4352;
        const float* Vb = Vs + buf * 4608;

        // ---- S = (Q*0.125) @ K^T, S in registers ----
        float sacc[8][4];
        #pragma unroll
        for (int nf = 0; nf < 8; nf++)
            #pragma unroll
            for (int i = 0; i < 4; i++) sacc[nf][i] = 0.0f;

        #pragma unroll
        for (int kk = 0; kk < 8; kk++) {
            uint32_t afr[4];
            afr[0] = Qsu[r0 * 68 + kk * 8 + t4];
            afr[1] = Qsu[(r0 + 8) * 68 + kk * 8 + t4];
            afr[2] = Qsu[r0 * 68 + kk * 8 + t4 + 4];
            afr[3] = Qsu[(r0 + 8) * 68 + kk * 8 + t4 + 4];
            uint32_t bfr[8][2];
            #pragma unroll
            for (int nf = 0; nf < 8; nf++) {
                int n = nf * 8 + g;
                bfr[nf][0] = f2tf(Kb[n * 68 + kk * 8 + t4]);
                bfr[nf][1] = f2tf(Kb[n * 68 + kk * 8 + t4 + 4]);
            }
            #pragma unroll
            for (int nf = 0; nf < 8; nf++)
                mma8(sacc[nf], afr, bfr[nf]);
        }

        // ---- mask + register softmax (quad shuffles) ----
        const float2* mf2 = (const float2*)(mfb + j * 64);
        float mx0 = -1e30f, mx1 = -1e30f;
        #pragma unroll
        for (int nf = 0; nf < 8; nf++) {
            float2 md = mf2[nf * 4 + t4];
            sacc[nf][0] += md.x; sacc[nf][1] += md.y;
            sacc[nf][2] += md.x; sacc[nf][3] += md.y;
            mx0 = fmaxf(mx0, fmaxf(sacc[nf][0], sacc[nf][1]));
            mx1 = fmaxf(mx1, fmaxf(sacc[nf][2], sacc[nf][3]));
        }
        mx0 = fmaxf(mx0, __shfl_xor_sync(0xffffffffu, mx0, 1));
        mx0 = fmaxf(mx0, __shfl_xor_sync(0xffffffffu, mx0, 2));
        mx1 = fmaxf(mx1, __shfl_xor_sync(0xffffffffu, mx1, 1));
        mx1 = fmaxf(mx1, __shfl_xor_sync(0xffffffffu, mx1, 2));
        float mn0 = fmaxf(m0, mx0), mn1 = fmaxf(m1, mx1);
        float c0 = __expf(m0 - mn0), c1 = __expf(m1 - mn1);
        float s0 = 0.0f, s1 = 0.0f;
        #pragma unroll
        for (int nf = 0; nf < 8; nf++) {
            float p00 = __expf(sacc[nf][0] - mn0);
            float p01 = __expf(sacc[nf][1] - mn0);
            float p10 = __expf(sacc[nf][2] - mn1);
            float p11 = __expf(sacc[nf][3] - mn1);
            s0 += p00 + p01; s1 += p10 + p11;
            sacc[nf][0] = __uint_as_float(f2tf(p00));
            sacc[nf][1] = __uint_as_float(f2tf(p01));
            sacc[nf][2] = __uint_as_float(f2tf(p10));
            sacc[nf][3] = __uint_as_float(f2tf(p11));
        }
        s0 += __shfl_xor_sync(0xffffffffu, s0, 1);
        s0 += __shfl_xor_sync(0xffffffffu, s0, 2);
        s1 += __shfl_xor_sync(0xffffffffu, s1, 1);
        s1 += __shfl_xor_sync(0xffffffffu, s1, 2);
        l0 = l0 * c0 + s0; l1 = l1 * c1 + s1;
        m0 = mn0; m1 = mn1;

        // ---- rescale O, accumulate P @ V ----
        #pragma unroll
        for (int nf = 0; nf < 8; nf++) {
            oacc[nf][0] *= c0; oacc[nf][1] *= c0;
            oacc[nf][2] *= c1; oacc[nf][3] *= c1;
        }
        #pragma unroll
        for (int kk = 0; kk < 8; kk++) {
            // gather P A-fragment from quad (acc layout -> A layout)
            float q00 = __shfl_sync(0xffffffffu, sacc[kk][0], lo + (t4 >> 1));
            float q01 = __shfl_sync(0xffffffffu, sacc[kk][1], lo + (t4 >> 1));
            float q10 = __shfl_sync(0xffffffffu, sacc[kk][2], lo + (t4 >> 1));
            float q11 = __shfl_sync(0xffffffffu, sacc[kk][3], lo + (t4 >> 1));
            float q20 = __shfl_sync(0xffffffffu, sacc[kk][0], lo + 2 + (t4 >> 1));
            float q21 = __shfl_sync(0xffffffffu, sacc[kk][1], lo + 2 + (t4 >> 1));
            float q30 = __shfl_sync(0xffffffffu, sacc[kk][2], lo + 2 + (t4 >> 1));
            float q31 = __shfl_sync(0xffffffffu, sacc[kk][3], lo + 2 + (t4 >> 1));
            bool odd = (t4 & 1);
            uint32_t afr[4];
            afr[0] = __float_as_uint(odd ? q01 : q00);   // P[r0][8kk+t4]
            afr[1] = __float_as_uint(odd ? q11 : q10);   // P[r1][8kk+t4]
            afr[2] = __float_as_uint(odd ? q21 : q20);   // P[r0][8kk+t4+4]
            afr[3] = __float_as_uint(odd ? q31 : q30);   // P[r1][8kk+t4+4]
            uint32_t bfr[8][2];
            #pragma unroll
            for (int nf = 0; nf < 8; nf++) {
                int n = nf * 8 + g;
                bfr[nf][0] = f2tf(Vb[(kk * 8 + t4) * 72 + n]);
                bfr[nf][1] = f2tf(Vb[(kk * 8 + t4 + 4) * 72 + n]);
            }
            #pragma unroll
            for (int nf = 0; nf < 8; nf++)
                mma8(oacc[nf], afr, bfr[nf]);
        }
        __syncthreads();   // all reads of this K/V buffer done before reuse
    }

    float inv0 = 1.0f / l0, inv1 = 1.0f / l1;
    float* Ob = Og + (size_t)tokbase * EDIM + h * HDIM;
    #pragma unroll
    for (int nf = 0; nf < 8; nf++) {
        int c = nf * 8 + 2 * t4;
        float2 o0, o1;
        o0.x = oacc[nf][0] * inv0; o0.y = oacc[nf][1] * inv0;
        o1.x = oacc[nf][2] * inv1; o1.y = oacc[nf][3] * inv1;
        *reinterpret_cast<float2*>(Ob + (size_t)r0 * EDIM + c)       = o0;
        *reinterpret_cast<float2*>(Ob + (size_t)(r0 + 8) * EDIM + c) = o1;
    }
}

// ------------------- NN tf32 GEMM, 3-stage cp.async pipeline -------------------
#define GEMM_SMEM_WORDS (3*4608 + 3*4352)

template<int EPI>
__global__ __launch_bounds__(256) void gemm_nn(
    const float* __restrict__ A, const float* __restrict__ Bm, float* __restrict__ C,
    int K, int N,
    const float* __restrict__ bias, const float* __restrict__ res)
{
    extern __shared__ float smf[];
    float* As = smf;
    float* Bs = smf + 3 * 4608;

    int m0 = blockIdx.y * 128, n0 = blockIdx.x * 128;
    int tid = threadIdx.x, warp = tid >> 5, lane = tid & 31;
    int wm = (warp >> 2) * 64, wn = (warp & 3) * 32;
    int g = lane >> 2, t4 = lane & 3;

    const int T = K >> 5;

    auto issue = [&](int t) {
        int s = t % 3;
        int k0 = t << 5;
        float* Ad = As + s * 4608;
        float* Bd = Bs + s * 4352;
        #pragma unroll
        for (int it = 0; it < 4; it++) {
            int idx = tid + it * 256;
            int r = idx >> 3, c4 = (idx & 7) * 4;
            CP16(&Ad[r * 36 + c4], A + (size_t)(m0 + r) * K + k0 + c4);
        }
        #pragma unroll
        for (int it = 0; it < 4; it++) {
            int idx = tid + it * 256;
            int r = idx >> 5, c4 = (idx & 31) * 4;
            CP16(&Bd[r * 136 + c4], Bm + (size_t)(k0 + r) * N + n0 + c4);
        }
    };

    float acc[4][4][4];
    #pragma unroll
    for (int a = 0; a < 4; a++)
        #pragma unroll
        for (int c = 0; c < 4; c++)
            #pragma unroll
            for (int i = 0; i < 4; i++) acc[a][c][i] = 0.0f;

    issue(0);
    CP_COMMIT();

    for (int t = 0; t < T; t++) {
        if (t + 1 < T) { issue(t + 1); CP_COMMIT(); CP_WAIT1(); }
        else           { CP_WAIT0(); }
        __syncthreads();

        const float* Af = As + (t % 3) * 4608;
        const float* Bf = Bs + (t % 3) * 4352;
        #pragma unroll
        for (int kk = 0; kk < 32; kk += 8) {
            uint32_t afr[4][4], bfr[4][2];
            #pragma unroll
            for (int mf = 0; mf < 4; mf++) {
                int mr = wm + mf * 16 + g;
                afr[mf][0] = f2tf(Af[mr * 36 + kk + t4]);
                afr[mf][1] = f2tf(Af[(mr + 8) * 36 + kk + t4]);
                afr[mf][2] = f2tf(Af[mr * 36 + kk + t4 + 4]);
                afr[mf][3] = f2tf(Af[(mr + 8) * 36 + kk + t4 + 4]);
            }
            #pragma unroll
            for (int nf = 0; nf < 4; nf++) {
                int n = wn + nf * 8 + g;
                bfr[nf][0] = f2tf(Bf[(kk + t4) * 136 + n]);
                bfr[nf][1] = f2tf(Bf[(kk + t4 + 4) * 136 + n]);
            }
            #pragma unroll
            for (int mf = 0; mf < 4; mf++)
                #pragma unroll
                for (int nf = 0; nf < 4; nf++)
                    mma8(acc[mf][nf], afr[mf], bfr[nf]);
        }
    }

    #pragma unroll
    for (int mf = 0; mf < 4; mf++) {
        #pragma unroll
        for (int nf = 0; nf < 4; nf++) {
            #pragma unroll
            for (int i = 0; i < 4; i++) {
                int m = m0 + wm + mf * 16 + g + ((i >= 2) ? 8 : 0);
                int n = n0 + wn + nf * 8 + 2 * t4 + (i & 1);
                float v = acc[mf][nf][i];
                if (EPI >= 1) v += bias[n];
                if (EPI == 2) v += res[(size_t)m * N + n];
                if (EPI == 3) v = gelu_exact(v);
                C[(size_t)m * N + n] = v;
            }
        }
    }
}

// ------------------- host launch -------------------
static float* sym_addr(const void* symbol) {
    void* p = nullptr;
    cudaGetSymbolAddress(&p, symbol);
    return reinterpret_cast<float*>(p);
}

extern "C" void kernel_launch(void* const* d_in, const int* in_sizes, int n_in,
                              void* d_out, int out_size) {
    (void)in_sizes; (void)n_in; (void)out_size;
    const float* value = (const float*)d_in[0];
    const float* key   = (const float*)d_in[1];
    const float* query = (const float*)d_in[2];
    const int*   mask  = (const int*)  d_in[3];
    const float* Wv    = (const float*)d_in[4];
    const float* Wk    = (const float*)d_in[5];
    const float* Wq    = (const float*)d_in[6];
    const float* Wo    = (const float*)d_in[7];
    const float* bo    = (const float*)d_in[8];
    const float* ln1_g = (const float*)d_in[9];
    const float* ln1_b = (const float*)d_in[10];
    const float* ln2_g = (const float*)d_in[11];
    const float* ln2_b = (const float*)d_in[12];
    const float* lnf_g = (const float*)d_in[13];
    const float* lnf_b = (const float*)d_in[14];
    const float* W1    = (const float*)d_in[15];
    const float* b1    = (const float*)d_in[16];
    const float* W2    = (const float*)d_in[17];
    const float* b2    = (const float*)d_in[18];
    float* out = (float*)d_out;

    float* p_qln = sym_addr(g_qln);
    float* p_vln = sym_addr(g_vln);
    float* p_kln = sym_addr(g_kln);
    float* p_Q   = sym_addr(g_Q);
    float* p_K   = sym_addr(g_K);
    float* p_V   = sym_addr(g_V);
    float* p_att = sym_addr(g_att);
    float* p_x   = sym_addr(g_x);
    float* p_h   = sym_addr(g_h);
    float* p_ff  = sym_addr(g_ff);
    float* p_mf  = sym_addr(g_maskf);

    const int GSM = GEMM_SMEM_WORDS * 4;     // 107520
    const int FSM = FLASH_SMEM_WORDS * 4;    // 106496
    cudaFuncSetAttribute(gemm_nn<0>, cudaFuncAttributeMaxDynamicSharedMemorySize, GSM);
    cudaFuncSetAttribute(gemm_nn<2>, cudaFuncAttributeMaxDynamicSharedMemorySize, GSM);
    cudaFuncSetAttribute(gemm_nn<3>, cudaFuncAttributeMaxDynamicSharedMemorySize, GSM);
    cudaFuncSetAttribute(flash_kernel, cudaFuncAttributeMaxDynamicSharedMemorySize, FSM);

    // 0) mask addends
    maskf_kernel<<<NTOK / 256, 256>>>(mask, p_mf);

    // 1) pre-norms
    ln_kernel<<<NTOK, 256>>>(query, p_qln, ln1_g, ln1_b);
    ln_kernel<<<NTOK, 256>>>(value, p_vln, ln2_g, ln2_b);
    ln_kernel<<<NTOK, 256>>>(key,   p_kln, ln2_g, ln2_b);

    // 2) QKV projections
    dim3 gProj(EDIM / 128, NTOK / 128, 1);
    gemm_nn<0><<<gProj, 256, GSM>>>(p_qln, Wq, p_Q, EDIM, EDIM, nullptr, nullptr);
    gemm_nn<0><<<gProj, 256, GSM>>>(p_kln, Wk, p_K, EDIM, EDIM, nullptr, nullptr);
    gemm_nn<0><<<gProj, 256, GSM>>>(p_vln, Wv, p_V, EDIM, EDIM, nullptr, nullptr);

    // 3) fused attention
    dim3 gF(SEQ / 128, NHEAD, BATCH);
    flash_kernel<<<gF, 256, FSM>>>(p_Q, p_K, p_V, p_mf, p_att);

    // 4) x = att @ Wo + bo + q_ln
    gemm_nn<2><<<gProj, 256, GSM>>>(p_att, Wo, p_x, EDIM, EDIM, bo, p_qln);

    // 5) h = LN_f(x)
    ln_kernel<<<NTOK, 256>>>(p_x, p_h, lnf_g, lnf_b);

    // 6) ff = gelu(h @ W1 + b1)
    dim3 gF1(FFDIM / 128, NTOK / 128, 1);
    gemm_nn<3><<<gF1, 256, GSM>>>(p_h, W1, p_ff, EDIM, FFDIM, b1, nullptr);

    // 7) out = ff @ W2 + b2 + x
    dim3 gF2(EDIM / 128, NTOK / 128, 1);
    gemm_nn<2><<<gF2, 256, GSM>>>(p_ff, W2, out, FFDIM, EDIM, b2, p_x);
}

// round 6
// speedup vs baseline: 2.7090x; 1.0552x over previous
#include <cuda_runtime.h>
#include <cstdint>
#include <cstddef>

#define EDIM 1024
#define NHEAD 16
#define HDIM 64
#define FFDIM 4096
#define BATCH 4
#define SEQ 2048
#define NTOK (BATCH*SEQ)   // 8192

// ------------------- scratch (device globals; no allocations) -------------------
__device__ float g_qlnr[(size_t)NTOK*EDIM];   // LN1(q) tf32-rounded (GEMM A)
__device__ float g_qln [(size_t)NTOK*EDIM];   // LN1(q) raw (residual)
__device__ float g_vln[(size_t)NTOK*EDIM];
__device__ float g_kln[(size_t)NTOK*EDIM];
__device__ float g_Q  [(size_t)NTOK*EDIM];
__device__ float g_K  [(size_t)NTOK*EDIM];
__device__ float g_V  [(size_t)NTOK*EDIM];
__device__ float g_att[(size_t)NTOK*EDIM];
__device__ float g_x  [(size_t)NTOK*EDIM];
__device__ float g_h  [(size_t)NTOK*EDIM];
__device__ float g_ff [(size_t)NTOK*FFDIM];
__device__ float g_maskf[(size_t)BATCH*SEQ];
__device__ float g_Wq[(size_t)EDIM*EDIM];
__device__ float g_Wk[(size_t)EDIM*EDIM];
__device__ float g_Wv[(size_t)EDIM*EDIM];
__device__ float g_Wo[(size_t)EDIM*EDIM];
__device__ float g_W1[(size_t)EDIM*FFDIM];
__device__ float g_W2[(size_t)FFDIM*EDIM];

// ------------------- helpers -------------------
__device__ __forceinline__ uint32_t f2tf(float f) {
    uint32_t u;
    asm("cvt.rna.tf32.f32 %0, %1;" : "=r"(u) : "f"(f));
    return u;
}
__device__ __forceinline__ float f2tf_f(float f) { return __uint_as_float(f2tf(f)); }

__device__ __forceinline__ void mma8(float* c, const uint32_t* a, const uint32_t* b) {
    asm volatile(
        "mma.sync.aligned.m16n8k8.row.col.f32.tf32.tf32.f32 "
        "{%0,%1,%2,%3},{%4,%5,%6,%7},{%8,%9},{%0,%1,%2,%3};\n"
        : "+f"(c[0]), "+f"(c[1]), "+f"(c[2]), "+f"(c[3])
        : "r"(a[0]), "r"(a[1]), "r"(a[2]), "r"(a[3]), "r"(b[0]), "r"(b[1]));
}

__device__ __forceinline__ float gelu_exact(float v) {
    return 0.5f * v * (1.0f + erff(v * 0.70710678118654752f));
}

#define CP16(dst_sm, src_g) \
    asm volatile("cp.async.cg.shared.global [%0], [%1], 16;\n" :: \
        "r"((uint32_t)__cvta_generic_to_shared(dst_sm)), "l"(src_g))
#define CP_COMMIT() asm volatile("cp.async.commit_group;\n")
#define CP_WAIT1()  asm volatile("cp.async.wait_group 1;\n")
#define CP_WAIT0()  asm volatile("cp.async.wait_group 0;\n")

// ------------------- mask -> float addend -------------------
__global__ __launch_bounds__(256) void maskf_kernel(
    const int* __restrict__ mask, float* __restrict__ mf)
{
    int i = blockIdx.x * 256 + threadIdx.x;
    mf[i] = (mask[i] == 0) ? -1e20f : 0.0f;
}

// ------------------- tf32 pre-round (weights) -------------------
__global__ __launch_bounds__(256) void round_kernel(
    const float* __restrict__ in, float* __restrict__ out)
{
    int i = (blockIdx.x * 256 + threadIdx.x) * 4;
    float4 v = *reinterpret_cast<const float4*>(in + i);
    float4 o;
    o.x = f2tf_f(v.x); o.y = f2tf_f(v.y); o.z = f2tf_f(v.z); o.w = f2tf_f(v.w);
    *reinterpret_cast<float4*>(out + i) = o;
}

// ------------------- LayerNorm (rounded out; optional raw out2) -------------------
__global__ __launch_bounds__(256) void ln_kernel(
    const float* __restrict__ in, float* __restrict__ out, float* __restrict__ out2,
    const float* __restrict__ gw, const float* __restrict__ gb)
{
    int row = blockIdx.x;
    int tid = threadIdx.x;
    const float4* inr = reinterpret_cast<const float4*>(in + (size_t)row * EDIM);
    float4 v = inr[tid];
    float s  = v.x + v.y + v.z + v.w;
    float sq = v.x*v.x + v.y*v.y + v.z*v.z + v.w*v.w;

    int lane = tid & 31, warp = tid >> 5;
    #pragma unroll
    for (int o = 16; o > 0; o >>= 1) {
        s  += __shfl_xor_sync(0xffffffffu, s, o);
        sq += __shfl_xor_sync(0xffffffffu, sq, o);
    }
    __shared__ float rs[8], rq[8];
    if (lane == 0) { rs[warp] = s; rq[warp] = sq; }
    __syncthreads();
    if (warp == 0) {
        float s2 = (lane < 8) ? rs[lane] : 0.0f;
        float q2 = (lane < 8) ? rq[lane] : 0.0f;
        #pragma unroll
        for (int o = 4; o > 0; o >>= 1) {
            s2 += __shfl_xor_sync(0xffffffffu, s2, o);
            q2 += __shfl_xor_sync(0xffffffffu, q2, o);
        }
        if (lane == 0) { rs[0] = s2; rq[0] = q2; }
    }
    __syncthreads();
    float mean = rs[0] * (1.0f / EDIM);
    float var  = rq[0] * (1.0f / EDIM) - mean * mean;
    float rstd = rsqrtf(var + 1e-5f);

    float4 gg = reinterpret_cast<const float4*>(gw)[tid];
    float4 bb = reinterpret_cast<const float4*>(gb)[tid];
    float4 o4;
    o4.x = (v.x - mean) * rstd * gg.x + bb.x;
    o4.y = (v.y - mean) * rstd * gg.y + bb.y;
    o4.z = (v.z - mean) * rstd * gg.z + bb.z;
    o4.w = (v.w - mean) * rstd * gg.w + bb.w;
    if (out2) reinterpret_cast<float4*>(out2 + (size_t)row * EDIM)[tid] = o4;
    float4 r4;
    r4.x = f2tf_f(o4.x); r4.y = f2tf_f(o4.y); r4.z = f2tf_f(o4.z); r4.w = f2tf_f(o4.w);
    reinterpret_cast<float4*>(out + (size_t)row * EDIM)[tid] = r4;
}

// ------------------- flash attention v2 (register softmax, no mainloop cvt) -------------------
// Inputs Q/K/V are tf32-pre-rounded. grid (16,16,4), 256 thr, 2 CTAs/SM.
// smem words: Qs [0,8704) 128x68 (Q*0.125, rounded); Ks [8704,17408) 2x64x68;
//             Vs [17408,26624) 2x64x72.
#define FLASH_SMEM_WORDS 26624

__global__ __launch_bounds__(256, 2) void flash_kernel(
    const float* __restrict__ Qg, const float* __restrict__ Kg,
    const float* __restrict__ Vg, const float* __restrict__ maskf,
    float* __restrict__ Og)
{
    extern __shared__ float sm[];
    float*    Qs = sm;
    float*    Ks = sm + 8704;
    float*    Vs = sm + 17408;
    uint32_t* Qsu = (uint32_t*)Qs;
    uint32_t* Ksu = (uint32_t*)Ks;
    uint32_t* Vsu = (uint32_t*)Vs;

    int qt = blockIdx.x, h = blockIdx.y, b = blockIdx.z;
    int tokbase = b * SEQ + qt * 128;
    const float* Qb  = Qg + (size_t)tokbase * EDIM + h * HDIM;
    const float* Kb0 = Kg + (size_t)b * SEQ * EDIM + h * HDIM;
    const float* Vb0 = Vg + (size_t)b * SEQ * EDIM + h * HDIM;
    const float* mfb = maskf + (size_t)b * SEQ;

    int tid = threadIdx.x, w = tid >> 5, lane = tid & 31;
    int g = lane >> 2, t4 = lane & 3;
    int r0 = w * 16 + g;
    int lo = lane & ~3;

    // stage Q tile: *0.125 (exact pow2, stays tf32-rounded)
    #pragma unroll
    for (int it = 0; it < 8; it++) {
        int idx = tid + it * 256;
        int r = idx >> 4, c4 = (idx & 15) * 4;
        float4 v = *reinterpret_cast<const float4*>(Qb + (size_t)r * EDIM + c4);
        float4 pk;
        pk.x = v.x * 0.125f; pk.y = v.y * 0.125f;
        pk.z = v.z * 0.125f; pk.w = v.w * 0.125f;
        *reinterpret_cast<float4*>(&Qs[r * 68 + c4]) = pk;
    }

    auto issue_kv = [&](int j, int buf) {
        const float* Kc = Kb0 + (size_t)j * 64 * EDIM;
        const float* Vc = Vb0 + (size_t)j * 64 * EDIM;
        float* Kd = Ks + buf * 4352;
        float* Vd = Vs + buf * 4608;
        #pragma unroll
        for (int it = 0; it < 4; it++) {
            int idx = tid + it * 256;
            int r = idx >> 4, c4 = (idx & 15) * 4;
            CP16(&Kd[r * 68 + c4], Kc + (size_t)r * EDIM + c4);
        }
        #pragma unroll
        for (int it = 0; it < 4; it++) {
            int idx = tid + it * 256;
            int r = idx >> 4, c4 = (idx & 15) * 4;
            CP16(&Vd[r * 72 + c4], Vc + (size_t)r * EDIM + c4);
        }
    };

    issue_kv(0, 0);
    CP_COMMIT();

    float m0 = -1e30f, m1 = -1e30f, l0 = 0.0f, l1 = 0.0f;
    float oacc[8][4];
    #pragma unroll
    for (int nf = 0; nf < 8; nf++)
        #pragma unroll
        for (int i = 0; i < 4; i++) oacc[nf][i] = 0.0f;

    const int NCH = SEQ / 64;
    for (int j = 0; j < NCH; j++) {
        int buf = j & 1;
        if (j + 1 < NCH) { issue_kv(j + 1, buf ^ 1); CP_COMMIT(); CP_WAIT1(); }
        else             { CP_WAIT0(); }
        __syncthreads();

        const uint32_t* Kb = Ksu + buf * 4352;
        const uint32_t* Vb = Vsu + buf * 4608;

        float sacc[8][4];
        #pragma unroll
        for (int nf = 0; nf < 8; nf++)
            #pragma unroll
            for (int i = 0; i < 4; i++) sacc[nf][i] = 0.0f;

        #pragma unroll
        for (int kk = 0; kk < 8; kk++) {
            uint32_t afr[4];
            afr[0] = Qsu[r0 * 68 + kk * 8 + t4];
            afr[1] = Qsu[(r0 + 8) * 68 + kk * 8 + t4];
            afr[2] = Qsu[r0 * 68 + kk * 8 + t4 + 4];
            afr[3] = Qsu[(r0 + 8) * 68 + kk * 8 + t4 + 4];
            uint32_t bfr[8][2];
            #pragma unroll
            for (int nf = 0; nf < 8; nf++) {
                int n = nf * 8 + g;
                bfr[nf][0] = Kb[n * 68 + kk * 8 + t4];
                bfr[nf][1] = Kb[n * 68 + kk * 8 + t4 + 4];
            }
            #pragma unroll
            for (int nf = 0; nf < 8; nf++)
                mma8(sacc[nf], afr, bfr[nf]);
        }

        const float2* mf2 = (const float2*)(mfb + j * 64);
        float mx0 = -1e30f, mx1 = -1e30f;
        #pragma unroll
        for (int nf = 0; nf < 8; nf++) {
            float2 md = mf2[nf * 4 + t4];
            sacc[nf][0] += md.x; sacc[nf][1] += md.y;
            sacc[nf][2] += md.x; sacc[nf][3] += md.y;
            mx0 = fmaxf(mx0, fmaxf(sacc[nf][0], sacc[nf][1]));
            mx1 = fmaxf(mx1, fmaxf(sacc[nf][2], sacc[nf][3]));
        }
        mx0 = fmaxf(mx0, __shfl_xor_sync(0xffffffffu, mx0, 1));
        mx0 = fmaxf(mx0, __shfl_xor_sync(0xffffffffu, mx0, 2));
        mx1 = fmaxf(mx1, __shfl_xor_sync(0xffffffffu, mx1, 1));
        mx1 = fmaxf(mx1, __shfl_xor_sync(0xffffffffu, mx1, 2));
        float mn0 = fmaxf(m0, mx0), mn1 = fmaxf(m1, mx1);
        float c0 = __expf(m0 - mn0), c1 = __expf(m1 - mn1);
        float s0 = 0.0f, s1 = 0.0f;
        #pragma unroll
        for (int nf = 0; nf < 8; nf++) {
            float p00 = __expf(sacc[nf][0] - mn0);
            float p01 = __expf(sacc[nf][1] - mn0);
            float p10 = __expf(sacc[nf][2] - mn1);
            float p11 = __expf(sacc[nf][3] - mn1);
            s0 += p00 + p01; s1 += p10 + p11;
            sacc[nf][0] = __uint_as_float(f2tf(p00));
            sacc[nf][1] = __uint_as_float(f2tf(p01));
            sacc[nf][2] = __uint_as_float(f2tf(p10));
            sacc[nf][3] = __uint_as_float(f2tf(p11));
        }
        s0 += __shfl_xor_sync(0xffffffffu, s0, 1);
        s0 += __shfl_xor_sync(0xffffffffu, s0, 2);
        s1 += __shfl_xor_sync(0xffffffffu, s1, 1);
        s1 += __shfl_xor_sync(0xffffffffu, s1, 2);
        l0 = l0 * c0 + s0; l1 = l1 * c1 + s1;
        m0 = mn0; m1 = mn1;

        #pragma unroll
        for (int nf = 0; nf < 8; nf++) {
            oacc[nf][0] *= c0; oacc[nf][1] *= c0;
            oacc[nf][2] *= c1; oacc[nf][3] *= c1;
        }
        #pragma unroll
        for (int kk = 0; kk < 8; kk++) {
            float q00 = __shfl_sync(0xffffffffu, sacc[kk][0], lo + (t4 >> 1));
            float q01 = __shfl_sync(0xffffffffu, sacc[kk][1], lo + (t4 >> 1));
            float q10 = __shfl_sync(0xffffffffu, sacc[kk][2], lo + (t4 >> 1));
            float q11 = __shfl_sync(0xffffffffu, sacc[kk][3], lo + (t4 >> 1));
            float q20 = __shfl_sync(0xffffffffu, sacc[kk][0], lo + 2 + (t4 >> 1));
            float q21 = __shfl_sync(0xffffffffu, sacc[kk][1], lo + 2 + (t4 >> 1));
            float q30 = __shfl_sync(0xffffffffu, sacc[kk][2], lo + 2 + (t4 >> 1));
            float q31 = __shfl_sync(0xffffffffu, sacc[kk][3], lo + 2 + (t4 >> 1));
            bool odd = (t4 & 1);
            uint32_t afr[4];
            afr[0] = __float_as_uint(odd ? q01 : q00);
            afr[1] = __float_as_uint(odd ? q11 : q10);
            afr[2] = __float_as_uint(odd ? q21 : q20);
            afr[3] = __float_as_uint(odd ? q31 : q30);
            uint32_t bfr[8][2];
            #pragma unroll
            for (int nf = 0; nf < 8; nf++) {
                int n = nf * 8 + g;
                bfr[nf][0] = Vb[(kk * 8 + t4) * 72 + n];
                bfr[nf][1] = Vb[(kk * 8 + t4 + 4) * 72 + n];
            }
            #pragma unroll
            for (int nf = 0; nf < 8; nf++)
                mma8(oacc[nf], afr, bfr[nf]);
        }
        __syncthreads();
    }

    float inv0 = 1.0f / l0, inv1 = 1.0f / l1;
    float* Ob = Og + (size_t)tokbase * EDIM + h * HDIM;
    #pragma unroll
    for (int nf = 0; nf < 8; nf++) {
        int c = nf * 8 + 2 * t4;
        float2 o0, o1;
        o0.x = f2tf_f(oacc[nf][0] * inv0); o0.y = f2tf_f(oacc[nf][1] * inv0);
        o1.x = f2tf_f(oacc[nf][2] * inv1); o1.y = f2tf_f(oacc[nf][3] * inv1);
        *reinterpret_cast<float2*>(Ob + (size_t)r0 * EDIM + c)       = o0;
        *reinterpret_cast<float2*>(Ob + (size_t)(r0 + 8) * EDIM + c) = o1;
    }
}

// ------------------- NN tf32 GEMM, 2-stage cp.async, 2 CTAs/SM -------------------
// Inputs pre-rounded to tf32 -> fragments load raw (no cvt).
// EPI: 0 none, 2 +bias+res, 3 gelu(acc+bias). RND: round output to tf32.
#define GEMM_SMEM_WORDS (2*4608 + 2*4352)

template<int EPI, int RND>
__global__ __launch_bounds__(256, 2) void gemm_nn(
    const float* __restrict__ A, const float* __restrict__ Bm, float* __restrict__ C,
    int K, int N,
    const float* __restrict__ bias, const float* __restrict__ res)
{
    extern __shared__ float smf[];
    float* As = smf;
    float* Bs = smf + 2 * 4608;
    uint32_t* Asu = (uint32_t*)As;
    uint32_t* Bsu = (uint32_t*)Bs;

    int m0 = blockIdx.y * 128, n0 = blockIdx.x * 128;
    int tid = threadIdx.x, warp = tid >> 5, lane = tid & 31;
    int wm = (warp >> 2) * 64, wn = (warp & 3) * 32;
    int g = lane >> 2, t4 = lane & 3;

    const int T = K >> 5;

    auto issue = [&](int t) {
        int s = t & 1;
        int k0 = t << 5;
        float* Ad = As + s * 4608;
        float* Bd = Bs + s * 4352;
        #pragma unroll
        for (int it = 0; it < 4; it++) {
            int idx = tid + it * 256;
            int r = idx >> 3, c4 = (idx & 7) * 4;
            CP16(&Ad[r * 36 + c4], A + (size_t)(m0 + r) * K + k0 + c4);
        }
        #pragma unroll
        for (int it = 0; it < 4; it++) {
            int idx = tid + it * 256;
            int r = idx >> 5, c4 = (idx & 31) * 4;
            CP16(&Bd[r * 136 + c4], Bm + (size_t)(k0 + r) * N + n0 + c4);
        }
    };

    float acc[4][4][4];
    #pragma unroll
    for (int a = 0; a < 4; a++)
        #pragma unroll
        for (int c = 0; c < 4; c++)
            #pragma unroll
            for (int i = 0; i < 4; i++) acc[a][c][i] = 0.0f;

    issue(0);
    CP_COMMIT();

    for (int t = 0; t < T; t++) {
        CP_WAIT0();
        __syncthreads();
        if (t + 1 < T) { issue(t + 1); CP_COMMIT(); }

        const uint32_t* Af = Asu + (t & 1) * 4608;
        const uint32_t* Bf = Bsu + (t & 1) * 4352;
        #pragma unroll
        for (int kk = 0; kk < 32; kk += 8) {
            uint32_t afr[4][4], bfr[4][2];
            #pragma unroll
            for (int mf = 0; mf < 4; mf++) {
                int mr = wm + mf * 16 + g;
                afr[mf][0] = Af[mr * 36 + kk + t4];
                afr[mf][1] = Af[(mr + 8) * 36 + kk + t4];
                afr[mf][2] = Af[mr * 36 + kk + t4 + 4];
                afr[mf][3] = Af[(mr + 8) * 36 + kk + t4 + 4];
            }
            #pragma unroll
            for (int nf = 0; nf < 4; nf++) {
                int n = wn + nf * 8 + g;
                bfr[nf][0] = Bf[(kk + t4) * 136 + n];
                bfr[nf][1] = Bf[(kk + t4 + 4) * 136 + n];
            }
            #pragma unroll
            for (int mf = 0; mf < 4; mf++)
                #pragma unroll
                for (int nf = 0; nf < 4; nf++)
                    mma8(acc[mf][nf], afr[mf], bfr[nf]);
        }
        __syncthreads();
    }

    #pragma unroll
    for (int mf = 0; mf < 4; mf++) {
        #pragma unroll
        for (int nf = 0; nf < 4; nf++) {
            #pragma unroll
            for (int i = 0; i < 4; i++) {
                int m = m0 + wm + mf * 16 + g + ((i >= 2) ? 8 : 0);
                int n = n0 + wn + nf * 8 + 2 * t4 + (i & 1);
                float v = acc[mf][nf][i];
                if (EPI >= 1) v += bias[n];
                if (EPI == 2) v += res[(size_t)m * N + n];
                if (EPI == 3) v = gelu_exact(v);
                if (RND) v = f2tf_f(v);
                C[(size_t)m * N + n] = v;
            }
        }
    }
}

// ------------------- host launch -------------------
static float* sym_addr(const void* symbol) {
    void* p = nullptr;
    cudaGetSymbolAddress(&p, symbol);
    return reinterpret_cast<float*>(p);
}

extern "C" void kernel_launch(void* const* d_in, const int* in_sizes, int n_in,
                              void* d_out, int out_size) {
    (void)in_sizes; (void)n_in; (void)out_size;
    const float* value = (const float*)d_in[0];
    const float* key   = (const float*)d_in[1];
    const float* query = (const float*)d_in[2];
    const int*   mask  = (const int*)  d_in[3];
    const float* Wv    = (const float*)d_in[4];
    const float* Wk    = (const float*)d_in[5];
    const float* Wq    = (const float*)d_in[6];
    const float* Wo    = (const float*)d_in[7];
    const float* bo    = (const float*)d_in[8];
    const float* ln1_g = (const float*)d_in[9];
    const float* ln1_b = (const float*)d_in[10];
    const float* ln2_g = (const float*)d_in[11];
    const float* ln2_b = (const float*)d_in[12];
    const float* lnf_g = (const float*)d_in[13];
    const float* lnf_b = (const float*)d_in[14];
    const float* W1    = (const float*)d_in[15];
    const float* b1    = (const float*)d_in[16];
    const float* W2    = (const float*)d_in[17];
    const float* b2    = (const float*)d_in[18];
    float* out = (float*)d_out;

    float* p_qlnr = sym_addr(g_qlnr);
    float* p_qln = sym_addr(g_qln);
    float* p_vln = sym_addr(g_vln);
    float* p_kln = sym_addr(g_kln);
    float* p_Q   = sym_addr(g_Q);
    float* p_K   = sym_addr(g_K);
    float* p_V   = sym_addr(g_V);
    float* p_att = sym_addr(g_att);
    float* p_x   = sym_addr(g_x);
    float* p_h   = sym_addr(g_h);
    float* p_ff  = sym_addr(g_ff);
    float* p_mf  = sym_addr(g_maskf);
    float* p_Wq  = sym_addr(g_Wq);
    float* p_Wk  = sym_addr(g_Wk);
    float* p_Wv  = sym_addr(g_Wv);
    float* p_Wo  = sym_addr(g_Wo);
    float* p_W1  = sym_addr(g_W1);
    float* p_W2  = sym_addr(g_W2);

    const int GSM = GEMM_SMEM_WORDS * 4;     // 71680
    const int FSM = FLASH_SMEM_WORDS * 4;    // 106496
    cudaFuncSetAttribute(gemm_nn<0,1>, cudaFuncAttributeMaxDynamicSharedMemorySize, GSM);
    cudaFuncSetAttribute(gemm_nn<2,0>, cudaFuncAttributeMaxDynamicSharedMemorySize, GSM);
    cudaFuncSetAttribute(gemm_nn<3,1>, cudaFuncAttributeMaxDynamicSharedMemorySize, GSM);
    cudaFuncSetAttribute(flash_kernel, cudaFuncAttributeMaxDynamicSharedMemorySize, FSM);

    // 0) mask addends + weight pre-round
    maskf_kernel<<<NTOK / 256, 256>>>(mask, p_mf);
    round_kernel<<<EDIM*EDIM/1024, 256>>>(Wq, p_Wq);
    round_kernel<<<EDIM*EDIM/1024, 256>>>(Wk, p_Wk);
    round_kernel<<<EDIM*EDIM/1024, 256>>>(Wv, p_Wv);
    round_kernel<<<EDIM*EDIM/1024, 256>>>(Wo, p_Wo);
    round_kernel<<<EDIM*FFDIM/1024, 256>>>(W1, p_W1);
    round_kernel<<<EDIM*FFDIM/1024, 256>>>(W2, p_W2);

    // 1) pre-norms (rounded outputs; raw copy of LN1(q) for residual)
    ln_kernel<<<NTOK, 256>>>(query, p_qlnr, p_qln, ln1_g, ln1_b);
    ln_kernel<<<NTOK, 256>>>(value, p_vln, nullptr, ln2_g, ln2_b);
    ln_kernel<<<NTOK, 256>>>(key,   p_kln, nullptr, ln2_g, ln2_b);

    // 2) QKV projections (rounded outputs)
    dim3 gProj(EDIM / 128, NTOK / 128, 1);
    gemm_nn<0,1><<<gProj, 256, GSM>>>(p_qlnr, p_Wq, p_Q, EDIM, EDIM, nullptr, nullptr);
    gemm_nn<0,1><<<gProj, 256, GSM>>>(p_kln, p_Wk, p_K, EDIM, EDIM, nullptr, nullptr);
    gemm_nn<0,1><<<gProj, 256, GSM>>>(p_vln, p_Wv, p_V, EDIM, EDIM, nullptr, nullptr);

    // 3) fused attention (rounded output)
    dim3 gF(SEQ / 128, NHEAD, BATCH);
    flash_kernel<<<gF, 256, FSM>>>(p_Q, p_K, p_V, p_mf, p_att);

    // 4) x = att @ Wo + bo + LN1(q)_raw   (unrounded)
    gemm_nn<2,0><<<gProj, 256, GSM>>>(p_att, p_Wo, p_x, EDIM, EDIM, bo, p_qln);

    // 5) h = LN_f(x) (rounded)
    ln_kernel<<<NTOK, 256>>>(p_x, p_h, nullptr, lnf_g, lnf_b);

    // 6) ff = gelu(h @ W1 + b1) (rounded)
    dim3 gF1(FFDIM / 128, NTOK / 128, 1);
    gemm_nn<3,1><<<gF1, 256, GSM>>>(p_h, p_W1, p_ff, EDIM, FFDIM, b1, nullptr);

    // 7) out = ff @ W2 + b2 + x (unrounded)
    dim3 gF2(EDIM / 128, NTOK / 128, 1);
    gemm_nn<2,0><<<gF2, 256, GSM>>>(p_ff, p_W2, out, FFDIM, EDIM, b2, p_x);
}

// round 7
// speedup vs baseline: 2.9628x; 1.0937x over previous
#include <cuda_runtime.h>
#include <cstdint>
#include <cstddef>

#define EDIM 1024
#define NHEAD 16
#define HDIM 64
#define FFDIM 4096
#define BATCH 4
#define SEQ 2048
#define NTOK (BATCH*SEQ)   // 8192

// ------------------- scratch (device globals; no allocations) -------------------
__device__ float g_qlnr[(size_t)NTOK*EDIM];   // LN1(q) tf32-rounded (GEMM A)
__device__ float g_qln [(size_t)NTOK*EDIM];   // LN1(q) raw (residual)
__device__ float g_vln[(size_t)NTOK*EDIM];
__device__ float g_kln[(size_t)NTOK*EDIM];
__device__ float g_Q  [(size_t)NTOK*EDIM];
__device__ float g_K  [(size_t)NTOK*EDIM];
__device__ float g_V  [(size_t)NTOK*EDIM];
__device__ float g_att[(size_t)NTOK*EDIM];
__device__ float g_x  [(size_t)NTOK*EDIM];
__device__ float g_h  [(size_t)NTOK*EDIM];
__device__ float g_ff [(size_t)NTOK*FFDIM];
__device__ float g_maskf[(size_t)BATCH*SEQ];
__device__ float g_Wq[(size_t)EDIM*EDIM];
__device__ float g_Wk[(size_t)EDIM*EDIM];
__device__ float g_Wv[(size_t)EDIM*EDIM];
__device__ float g_Wo[(size_t)EDIM*EDIM];
__device__ float g_W1[(size_t)EDIM*FFDIM];
__device__ float g_W2[(size_t)FFDIM*EDIM];

// ------------------- helpers -------------------
__device__ __forceinline__ uint32_t f2tf(float f) {
    uint32_t u;
    asm("cvt.rna.tf32.f32 %0, %1;" : "=r"(u) : "f"(f));
    return u;
}
__device__ __forceinline__ float f2tf_f(float f) { return __uint_as_float(f2tf(f)); }

__device__ __forceinline__ void mma8(float* c, const uint32_t* a, const uint32_t* b) {
    asm volatile(
        "mma.sync.aligned.m16n8k8.row.col.f32.tf32.tf32.f32 "
        "{%0,%1,%2,%3},{%4,%5,%6,%7},{%8,%9},{%0,%1,%2,%3};\n"
        : "+f"(c[0]), "+f"(c[1]), "+f"(c[2]), "+f"(c[3])
        : "r"(a[0]), "r"(a[1]), "r"(a[2]), "r"(a[3]), "r"(b[0]), "r"(b[1]));
}

__device__ __forceinline__ float gelu_exact(float v) {
    return 0.5f * v * (1.0f + erff(v * 0.70710678118654752f));
}

#define CP16(dst_sm, src_g) \
    asm volatile("cp.async.cg.shared.global [%0], [%1], 16;\n" :: \
        "r"((uint32_t)__cvta_generic_to_shared(dst_sm)), "l"(src_g))
#define CP_COMMIT() asm volatile("cp.async.commit_group;\n")
#define CP_WAIT1()  asm volatile("cp.async.wait_group 1;\n")
#define CP_WAIT0()  asm volatile("cp.async.wait_group 0;\n")

// ------------------- mask -> float addend -------------------
__global__ __launch_bounds__(256) void maskf_kernel(
    const int* __restrict__ mask, float* __restrict__ mf)
{
    int i = blockIdx.x * 256 + threadIdx.x;
    mf[i] = (mask[i] == 0) ? -1e20f : 0.0f;
}

// ------------------- tf32 pre-round (weights) -------------------
__global__ __launch_bounds__(256) void round_kernel(
    const float* __restrict__ in, float* __restrict__ out)
{
    int i = (blockIdx.x * 256 + threadIdx.x) * 4;
    float4 v = *reinterpret_cast<const float4*>(in + i);
    float4 o;
    o.x = f2tf_f(v.x); o.y = f2tf_f(v.y); o.z = f2tf_f(v.z); o.w = f2tf_f(v.w);
    *reinterpret_cast<float4*>(out + i) = o;
}

// ------------------- LayerNorm (rounded out; optional raw out2) -------------------
__global__ __launch_bounds__(256) void ln_kernel(
    const float* __restrict__ in, float* __restrict__ out, float* __restrict__ out2,
    const float* __restrict__ gw, const float* __restrict__ gb)
{
    int row = blockIdx.x;
    int tid = threadIdx.x;
    const float4* inr = reinterpret_cast<const float4*>(in + (size_t)row * EDIM);
    float4 v = inr[tid];
    float s  = v.x + v.y + v.z + v.w;
    float sq = v.x*v.x + v.y*v.y + v.z*v.z + v.w*v.w;

    int lane = tid & 31, warp = tid >> 5;
    #pragma unroll
    for (int o = 16; o > 0; o >>= 1) {
        s  += __shfl_xor_sync(0xffffffffu, s, o);
        sq += __shfl_xor_sync(0xffffffffu, sq, o);
    }
    __shared__ float rs[8], rq[8];
    if (lane == 0) { rs[warp] = s; rq[warp] = sq; }
    __syncthreads();
    if (warp == 0) {
        float s2 = (lane < 8) ? rs[lane] : 0.0f;
        float q2 = (lane < 8) ? rq[lane] : 0.0f;
        #pragma unroll
        for (int o = 4; o > 0; o >>= 1) {
            s2 += __shfl_xor_sync(0xffffffffu, s2, o);
            q2 += __shfl_xor_sync(0xffffffffu, q2, o);
        }
        if (lane == 0) { rs[0] = s2; rq[0] = q2; }
    }
    __syncthreads();
    float mean = rs[0] * (1.0f / EDIM);
    float var  = rq[0] * (1.0f / EDIM) - mean * mean;
    float rstd = rsqrtf(var + 1e-5f);

    float4 gg = reinterpret_cast<const float4*>(gw)[tid];
    float4 bb = reinterpret_cast<const float4*>(gb)[tid];
    float4 o4;
    o4.x = (v.x - mean) * rstd * gg.x + bb.x;
    o4.y = (v.y - mean) * rstd * gg.y + bb.y;
    o4.z = (v.z - mean) * rstd * gg.z + bb.z;
    o4.w = (v.w - mean) * rstd * gg.w + bb.w;
    if (out2) reinterpret_cast<float4*>(out2 + (size_t)row * EDIM)[tid] = o4;
    float4 r4;
    r4.x = f2tf_f(o4.x); r4.y = f2tf_f(o4.y); r4.z = f2tf_f(o4.z); r4.w = f2tf_f(o4.w);
    reinterpret_cast<float4*>(out + (size_t)row * EDIM)[tid] = r4;
}

// ------------------- flash attention v2 (register softmax, no mainloop cvt) -------------------
// Inputs Q/K/V are tf32-pre-rounded. grid (16,16,4), 256 thr, 2 CTAs/SM.
#define FLASH_SMEM_WORDS 26624

__global__ __launch_bounds__(256, 2) void flash_kernel(
    const float* __restrict__ Qg, const float* __restrict__ Kg,
    const float* __restrict__ Vg, const float* __restrict__ maskf,
    float* __restrict__ Og)
{
    extern __shared__ float sm[];
    float*    Qs = sm;
    float*    Ks = sm + 8704;
    float*    Vs = sm + 17408;
    uint32_t* Qsu = (uint32_t*)Qs;
    uint32_t* Ksu = (uint32_t*)Ks;
    uint32_t* Vsu = (uint32_t*)Vs;

    int qt = blockIdx.x, h = blockIdx.y, b = blockIdx.z;
    int tokbase = b * SEQ + qt * 128;
    const float* Qb  = Qg + (size_t)tokbase * EDIM + h * HDIM;
    const float* Kb0 = Kg + (size_t)b * SEQ * EDIM + h * HDIM;
    const float* Vb0 = Vg + (size_t)b * SEQ * EDIM + h * HDIM;
    const float* mfb = maskf + (size_t)b * SEQ;

    int tid = threadIdx.x, w = tid >> 5, lane = tid & 31;
    int g = lane >> 2, t4 = lane & 3;
    int r0 = w * 16 + g;
    int lo = lane & ~3;

    #pragma unroll
    for (int it = 0; it < 8; it++) {
        int idx = tid + it * 256;
        int r = idx >> 4, c4 = (idx & 15) * 4;
        float4 v = *reinterpret_cast<const float4*>(Qb + (size_t)r * EDIM + c4);
        float4 pk;
        pk.x = v.x * 0.125f; pk.y = v.y * 0.125f;
        pk.z = v.z * 0.125f; pk.w = v.w * 0.125f;
        *reinterpret_cast<float4*>(&Qs[r * 68 + c4]) = pk;
    }

    auto issue_kv = [&](int j, int buf) {
        const float* Kc = Kb0 + (size_t)j * 64 * EDIM;
        const float* Vc = Vb0 + (size_t)j * 64 * EDIM;
        float* Kd = Ks + buf * 4352;
        float* Vd = Vs + buf * 4608;
        #pragma unroll
        for (int it = 0; it < 4; it++) {
            int idx = tid + it * 256;
            int r = idx >> 4, c4 = (idx & 15) * 4;
            CP16(&Kd[r * 68 + c4], Kc + (size_t)r * EDIM + c4);
        }
        #pragma unroll
        for (int it = 0; it < 4; it++) {
            int idx = tid + it * 256;
            int r = idx >> 4, c4 = (idx & 15) * 4;
            CP16(&Vd[r * 72 + c4], Vc + (size_t)r * EDIM + c4);
        }
    };

    issue_kv(0, 0);
    CP_COMMIT();

    float m0 = -1e30f, m1 = -1e30f, l0 = 0.0f, l1 = 0.0f;
    float oacc[8][4];
    #pragma unroll
    for (int nf = 0; nf < 8; nf++)
        #pragma unroll
        for (int i = 0; i < 4; i++) oacc[nf][i] = 0.0f;

    const int NCH = SEQ / 64;
    for (int j = 0; j < NCH; j++) {
        int buf = j & 1;
        if (j + 1 < NCH) { issue_kv(j + 1, buf ^ 1); CP_COMMIT(); CP_WAIT1(); }
        else             { CP_WAIT0(); }
        __syncthreads();

        const uint32_t* Kb = Ksu + buf * 4352;
        const uint32_t* Vb = Vsu + buf * 4608;

        float sacc[8][4];
        #pragma unroll
        for (int nf = 0; nf < 8; nf++)
            #pragma unroll
            for (int i = 0; i < 4; i++) sacc[nf][i] = 0.0f;

        #pragma unroll
        for (int kk = 0; kk < 8; kk++) {
            uint32_t afr[4];
            afr[0] = Qsu[r0 * 68 + kk * 8 + t4];
            afr[1] = Qsu[(r0 + 8) * 68 + kk * 8 + t4];
            afr[2] = Qsu[r0 * 68 + kk * 8 + t4 + 4];
            afr[3] = Qsu[(r0 + 8) * 68 + kk * 8 + t4 + 4];
            uint32_t bfr[8][2];
            #pragma unroll
            for (int nf = 0; nf < 8; nf++) {
                int n = nf * 8 + g;
                bfr[nf][0] = Kb[n * 68 + kk * 8 + t4];
                bfr[nf][1] = Kb[n * 68 + kk * 8 + t4 + 4];
            }
            #pragma unroll
            for (int nf = 0; nf < 8; nf++)
                mma8(sacc[nf], afr, bfr[nf]);
        }

        const float2* mf2 = (const float2*)(mfb + j * 64);
        float mx0 = -1e30f, mx1 = -1e30f;
        #pragma unroll
        for (int nf = 0; nf < 8; nf++) {
            float2 md = mf2[nf * 4 + t4];
            sacc[nf][0] += md.x; sacc[nf][1] += md.y;
            sacc[nf][2] += md.x; sacc[nf][3] += md.y;
            mx0 = fmaxf(mx0, fmaxf(sacc[nf][0], sacc[nf][1]));
            mx1 = fmaxf(mx1, fmaxf(sacc[nf][2], sacc[nf][3]));
        }
        mx0 = fmaxf(mx0, __shfl_xor_sync(0xffffffffu, mx0, 1));
        mx0 = fmaxf(mx0, __shfl_xor_sync(0xffffffffu, mx0, 2));
        mx1 = fmaxf(mx1, __shfl_xor_sync(0xffffffffu, mx1, 1));
        mx1 = fmaxf(mx1, __shfl_xor_sync(0xffffffffu, mx1, 2));
        float mn0 = fmaxf(m0, mx0), mn1 = fmaxf(m1, mx1);
        float c0 = __expf(m0 - mn0), c1 = __expf(m1 - mn1);
        float s0 = 0.0f, s1 = 0.0f;
        #pragma unroll
        for (int nf = 0; nf < 8; nf++) {
            float p00 = __expf(sacc[nf][0] - mn0);
            float p01 = __expf(sacc[nf][1] - mn0);
            float p10 = __expf(sacc[nf][2] - mn1);
            float p11 = __expf(sacc[nf][3] - mn1);
            s0 += p00 + p01; s1 += p10 + p11;
            sacc[nf][0] = __uint_as_float(f2tf(p00));
            sacc[nf][1] = __uint_as_float(f2tf(p01));
            sacc[nf][2] = __uint_as_float(f2tf(p10));
            sacc[nf][3] = __uint_as_float(f2tf(p11));
        }
        s0 += __shfl_xor_sync(0xffffffffu, s0, 1);
        s0 += __shfl_xor_sync(0xffffffffu, s0, 2);
        s1 += __shfl_xor_sync(0xffffffffu, s1, 1);
        s1 += __shfl_xor_sync(0xffffffffu, s1, 2);
        l0 = l0 * c0 + s0; l1 = l1 * c1 + s1;
        m0 = mn0; m1 = mn1;

        #pragma unroll
        for (int nf = 0; nf < 8; nf++) {
            oacc[nf][0] *= c0; oacc[nf][1] *= c0;
            oacc[nf][2] *= c1; oacc[nf][3] *= c1;
        }
        #pragma unroll
        for (int kk = 0; kk < 8; kk++) {
            float q00 = __shfl_sync(0xffffffffu, sacc[kk][0], lo + (t4 >> 1));
            float q01 = __shfl_sync(0xffffffffu, sacc[kk][1], lo + (t4 >> 1));
            float q10 = __shfl_sync(0xffffffffu, sacc[kk][2], lo + (t4 >> 1));
            float q11 = __shfl_sync(0xffffffffu, sacc[kk][3], lo + (t4 >> 1));
            float q20 = __shfl_sync(0xffffffffu, sacc[kk][0], lo + 2 + (t4 >> 1));
            float q21 = __shfl_sync(0xffffffffu, sacc[kk][1], lo + 2 + (t4 >> 1));
            float q30 = __shfl_sync(0xffffffffu, sacc[kk][2], lo + 2 + (t4 >> 1));
            float q31 = __shfl_sync(0xffffffffu, sacc[kk][3], lo + 2 + (t4 >> 1));
            bool odd = (t4 & 1);
            uint32_t afr[4];
            afr[0] = __float_as_uint(odd ? q01 : q00);
            afr[1] = __float_as_uint(odd ? q11 : q10);
            afr[2] = __float_as_uint(odd ? q21 : q20);
            afr[3] = __float_as_uint(odd ? q31 : q30);
            uint32_t bfr[8][2];
            #pragma unroll
            for (int nf = 0; nf < 8; nf++) {
                int n = nf * 8 + g;
                bfr[nf][0] = Vb[(kk * 8 + t4) * 72 + n];
                bfr[nf][1] = Vb[(kk * 8 + t4 + 4) * 72 + n];
            }
            #pragma unroll
            for (int nf = 0; nf < 8; nf++)
                mma8(oacc[nf], afr, bfr[nf]);
        }
        __syncthreads();
    }

    float inv0 = 1.0f / l0, inv1 = 1.0f / l1;
    float* Ob = Og + (size_t)tokbase * EDIM + h * HDIM;
    #pragma unroll
    for (int nf = 0; nf < 8; nf++) {
        int c = nf * 8 + 2 * t4;
        float2 o0, o1;
        o0.x = f2tf_f(oacc[nf][0] * inv0); o0.y = f2tf_f(oacc[nf][1] * inv0);
        o1.x = f2tf_f(oacc[nf][2] * inv1); o1.y = f2tf_f(oacc[nf][3] * inv1);
        *reinterpret_cast<float2*>(Ob + (size_t)r0 * EDIM + c)       = o0;
        *reinterpret_cast<float2*>(Ob + (size_t)(r0 + 8) * EDIM + c) = o1;
    }
}

// ------------------- NN tf32 GEMM, 3-stage cp.async, 2 CTAs/SM -------------------
// Inputs pre-rounded to tf32 -> fragments load raw (no cvt).
// EPI: 0 none, 2 +bias+res, 3 gelu(acc+bias). RND: round output to tf32.
#define GEMM_SMEM_WORDS (3*4608 + 3*4352)

template<int EPI, int RND>
__global__ __launch_bounds__(256, 2) void gemm_nn(
    const float* __restrict__ A, const float* __restrict__ Bm, float* __restrict__ C,
    int K, int N,
    const float* __restrict__ bias, const float* __restrict__ res)
{
    extern __shared__ float smf[];
    float* As = smf;
    float* Bs = smf + 3 * 4608;
    uint32_t* Asu = (uint32_t*)As;
    uint32_t* Bsu = (uint32_t*)Bs;

    int m0 = blockIdx.y * 128, n0 = blockIdx.x * 128;
    int tid = threadIdx.x, warp = tid >> 5, lane = tid & 31;
    int wm = (warp >> 2) * 64, wn = (warp & 3) * 32;
    int g = lane >> 2, t4 = lane & 3;

    const int T = K >> 5;

    auto issue = [&](int t) {
        int s = t % 3;
        int k0 = t << 5;
        float* Ad = As + s * 4608;
        float* Bd = Bs + s * 4352;
        #pragma unroll
        for (int it = 0; it < 4; it++) {
            int idx = tid + it * 256;
            int r = idx >> 3, c4 = (idx & 7) * 4;
            CP16(&Ad[r * 36 + c4], A + (size_t)(m0 + r) * K + k0 + c4);
        }
        #pragma unroll
        for (int it = 0; it < 4; it++) {
            int idx = tid + it * 256;
            int r = idx >> 5, c4 = (idx & 31) * 4;
            CP16(&Bd[r * 136 + c4], Bm + (size_t)(k0 + r) * N + n0 + c4);
        }
    };

    float acc[4][4][4];
    #pragma unroll
    for (int a = 0; a < 4; a++)
        #pragma unroll
        for (int c = 0; c < 4; c++)
            #pragma unroll
            for (int i = 0; i < 4; i++) acc[a][c][i] = 0.0f;

    issue(0);
    CP_COMMIT();

    for (int t = 0; t < T; t++) {
        if (t + 1 < T) { issue(t + 1); CP_COMMIT(); CP_WAIT1(); }
        else           { CP_WAIT0(); }
        __syncthreads();

        const uint32_t* Af = Asu + (t % 3) * 4608;
        const uint32_t* Bf = Bsu + (t % 3) * 4352;
        #pragma unroll
        for (int kk = 0; kk < 32; kk += 8) {
            uint32_t afr[4][4], bfr[4][2];
            #pragma unroll
            for (int mf = 0; mf < 4; mf++) {
                int mr = wm + mf * 16 + g;
                afr[mf][0] = Af[mr * 36 + kk + t4];
                afr[mf][1] = Af[(mr + 8) * 36 + kk + t4];
                afr[mf][2] = Af[mr * 36 + kk + t4 + 4];
                afr[mf][3] = Af[(mr + 8) * 36 + kk + t4 + 4];
            }
            #pragma unroll
            for (int nf = 0; nf < 4; nf++) {
                int n = wn + nf * 8 + g;
                bfr[nf][0] = Bf[(kk + t4) * 136 + n];
                bfr[nf][1] = Bf[(kk + t4 + 4) * 136 + n];
            }
            #pragma unroll
            for (int mf = 0; mf < 4; mf++)
                #pragma unroll
                for (int nf = 0; nf < 4; nf++)
                    mma8(acc[mf][nf], afr[mf], bfr[nf]);
        }
    }

    // vectorized epilogue: acc[..][0,1] adjacent cols; [2,3] same at m+8
    #pragma unroll
    for (int mf = 0; mf < 4; mf++) {
        #pragma unroll
        for (int nf = 0; nf < 4; nf++) {
            int m = m0 + wm + mf * 16 + g;
            int n = n0 + wn + nf * 8 + 2 * t4;
            float2 v0 = make_float2(acc[mf][nf][0], acc[mf][nf][1]);
            float2 v1 = make_float2(acc[mf][nf][2], acc[mf][nf][3]);
            if (EPI >= 1) {
                float2 bz = *reinterpret_cast<const float2*>(bias + n);
                v0.x += bz.x; v0.y += bz.y;
                v1.x += bz.x; v1.y += bz.y;
            }
            if (EPI == 2) {
                float2 r0 = *reinterpret_cast<const float2*>(res + (size_t)m * N + n);
                float2 r1 = *reinterpret_cast<const float2*>(res + (size_t)(m + 8) * N + n);
                v0.x += r0.x; v0.y += r0.y;
                v1.x += r1.x; v1.y += r1.y;
            }
            if (EPI == 3) {
                v0.x = gelu_exact(v0.x); v0.y = gelu_exact(v0.y);
                v1.x = gelu_exact(v1.x); v1.y = gelu_exact(v1.y);
            }
            if (RND) {
                v0.x = f2tf_f(v0.x); v0.y = f2tf_f(v0.y);
                v1.x = f2tf_f(v1.x); v1.y = f2tf_f(v1.y);
            }
            *reinterpret_cast<float2*>(C + (size_t)m * N + n)       = v0;
            *reinterpret_cast<float2*>(C + (size_t)(m + 8) * N + n) = v1;
        }
    }
}

// ------------------- host launch -------------------
static float* sym_addr(const void* symbol) {
    void* p = nullptr;
    cudaGetSymbolAddress(&p, symbol);
    return reinterpret_cast<float*>(p);
}

extern "C" void kernel_launch(void* const* d_in, const int* in_sizes, int n_in,
                              void* d_out, int out_size) {
    (void)in_sizes; (void)n_in; (void)out_size;
    const float* value = (const float*)d_in[0];
    const float* key   = (const float*)d_in[1];
    const float* query = (const float*)d_in[2];
    const int*   mask  = (const int*)  d_in[3];
    const float* Wv    = (const float*)d_in[4];
    const float* Wk    = (const float*)d_in[5];
    const float* Wq    = (const float*)d_in[6];
    const float* Wo    = (const float*)d_in[7];
    const float* bo    = (const float*)d_in[8];
    const float* ln1_g = (const float*)d_in[9];
    const float* ln1_b = (const float*)d_in[10];
    const float* ln2_g = (const float*)d_in[11];
    const float* ln2_b = (const float*)d_in[12];
    const float* lnf_g = (const float*)d_in[13];
    const float* lnf_b = (const float*)d_in[14];
    const float* W1    = (const float*)d_in[15];
    const float* b1    = (const float*)d_in[16];
    const float* W2    = (const float*)d_in[17];
    const float* b2    = (const float*)d_in[18];
    float* out = (float*)d_out;

    float* p_qlnr = sym_addr(g_qlnr);
    float* p_qln = sym_addr(g_qln);
    float* p_vln = sym_addr(g_vln);
    float* p_kln = sym_addr(g_kln);
    float* p_Q   = sym_addr(g_Q);
    float* p_K   = sym_addr(g_K);
    float* p_V   = sym_addr(g_V);
    float* p_att = sym_addr(g_att);
    float* p_x   = sym_addr(g_x);
    float* p_h   = sym_addr(g_h);
    float* p_ff  = sym_addr(g_ff);
    float* p_mf  = sym_addr(g_maskf);
    float* p_Wq  = sym_addr(g_Wq);
    float* p_Wk  = sym_addr(g_Wk);
    float* p_Wv  = sym_addr(g_Wv);
    float* p_Wo  = sym_addr(g_Wo);
    float* p_W1  = sym_addr(g_W1);
    float* p_W2  = sym_addr(g_W2);

    const int GSM = GEMM_SMEM_WORDS * 4;     // 107520
    const int FSM = FLASH_SMEM_WORDS * 4;    // 106496
    cudaFuncSetAttribute(gemm_nn<0,1>, cudaFuncAttributeMaxDynamicSharedMemorySize, GSM);
    cudaFuncSetAttribute(gemm_nn<2,0>, cudaFuncAttributeMaxDynamicSharedMemorySize, GSM);
    cudaFuncSetAttribute(gemm_nn<3,1>, cudaFuncAttributeMaxDynamicSharedMemorySize, GSM);
    cudaFuncSetAttribute(flash_kernel, cudaFuncAttributeMaxDynamicSharedMemorySize, FSM);

    // 0) mask addends + weight pre-round
    maskf_kernel<<<NTOK / 256, 256>>>(mask, p_mf);
    round_kernel<<<EDIM*EDIM/1024, 256>>>(Wq, p_Wq);
    round_kernel<<<EDIM*EDIM/1024, 256>>>(Wk, p_Wk);
    round_kernel<<<EDIM*EDIM/1024, 256>>>(Wv, p_Wv);
    round_kernel<<<EDIM*EDIM/1024, 256>>>(Wo, p_Wo);
    round_kernel<<<EDIM*FFDIM/1024, 256>>>(W1, p_W1);
    round_kernel<<<EDIM*FFDIM/1024, 256>>>(W2, p_W2);

    // 1) pre-norms (rounded outputs; raw copy of LN1(q) for residual)
    ln_kernel<<<NTOK, 256>>>(query, p_qlnr, p_qln, ln1_g, ln1_b);
    ln_kernel<<<NTOK, 256>>>(value, p_vln, nullptr, ln2_g, ln2_b);
    ln_kernel<<<NTOK, 256>>>(key,   p_kln, nullptr, ln2_g, ln2_b);

    // 2) QKV projections (rounded outputs)
    dim3 gProj(EDIM / 128, NTOK / 128, 1);
    gemm_nn<0,1><<<gProj, 256, GSM>>>(p_qlnr, p_Wq, p_Q, EDIM, EDIM, nullptr, nullptr);
    gemm_nn<0,1><<<gProj, 256, GSM>>>(p_kln, p_Wk, p_K, EDIM, EDIM, nullptr, nullptr);
    gemm_nn<0,1><<<gProj, 256, GSM>>>(p_vln, p_Wv, p_V, EDIM, EDIM, nullptr, nullptr);

    // 3) fused attention (rounded output)
    dim3 gF(SEQ / 128, NHEAD, BATCH);
    flash_kernel<<<gF, 256, FSM>>>(p_Q, p_K, p_V, p_mf, p_att);

    // 4) x = att @ Wo + bo + LN1(q)_raw   (unrounded)
    gemm_nn<2,0><<<gProj, 256, GSM>>>(p_att, p_Wo, p_x, EDIM, EDIM, bo, p_qln);

    // 5) h = LN_f(x) (rounded)
    ln_kernel<<<NTOK, 256>>>(p_x, p_h, nullptr, lnf_g, lnf_b);

    // 6) ff = gelu(h @ W1 + b1) (rounded)
    dim3 gF1(FFDIM / 128, NTOK / 128, 1);
    gemm_nn<3,1><<<gF1, 256, GSM>>>(p_h, p_W1, p_ff, EDIM, FFDIM, b1, nullptr);

    // 7) out = ff @ W2 + b2 + x (unrounded)
    dim3 gF2(EDIM / 128, NTOK / 128, 1);
    gemm_nn<2,0><<<gF2, 256, GSM>>>(p_ff, p_W2, out, FFDIM, EDIM, b2, p_x);
}